// round 10
// baseline (speedup 1.0000x reference)
#include <cuda_runtime.h>
#include <cstdint>

// ---------------- problem constants ----------------
#define BN   32
#define TN   4096
#define CINN 165
#define EDIM 64
#define NEMB 512
#define NTOK (BN*TN)          // 131072
#define TILE 64               // tokens per CTA
#define NBLK (NTOK/TILE)      // 2048
#define LDA  68               // padded token-row stride (floats)
#define DEC_ELEMS (NTOK*CINN) // 21626880
#define THREADS 256

// shared layout (floats): single in-place activation buffer A[288 rows]
#define AROWS  288
#define SM_A   0
#define SM_W   (AROWS*LDA)          // 19584
#define WBUFF  4096                 // floats per weight buffer (KBT*CW <= 4096)
#define SM_AUX (SM_W + 2*WBUFF)     // 27776
#define SM_FLOATS (SM_AUX + 256 + 64 + 8)
#define SMEM_BYTES (SM_FLOATS*4)    // ~112.4 KB -> 2 CTAs/SM

typedef unsigned long long ULL;

// transposed+padded weights and bias, built once per launch by prep_kernel
__device__ float g_Wt[276480];
__device__ float g_bias[2432];
__device__ float g_part[NBLK];
__device__ unsigned int g_count;

// layer metadata: {w_in_idx, b_in_idx, CIN, COUT, KPAD, CW, woff, boff}
__constant__ int c_layers[15][8] = {
    { 1,  2, 165, 128, 176, 128,      0,    0},
    { 3,  4, 128, 256, 128, 256,  22528,  128},
    { 5,  6, 256, 256, 256, 256,  55296,  384},
    { 7,  8, 256,  32, 256,  32, 120832,  640},
    { 9, 10,  32, 256,  32, 256, 129024,  672},
    {11, 12, 256,  32, 256,  32, 137216,  928},
    {13, 14,  32, 256,  32, 256, 145408,  960},
    {15, 16, 256,  64, 256,  64, 153600, 1216},
    {18, 19,  64, 256,  64, 256, 169984, 1280},
    {20, 21, 256,  32, 256,  32, 186368, 1536},
    {22, 23,  32, 256,  32, 256, 194560, 1568},
    {24, 25, 256,  32, 256,  32, 202752, 1824},
    {26, 27,  32, 256,  32, 256, 210944, 1856},
    {28, 29, 256, 128, 256, 128, 219136, 2112},
    {30, 31, 128, 165, 128, 192, 251904, 2240},
};

// ---------------- f32x2 helpers ----------------
__device__ __forceinline__ ULL pack2(float x, float y) {
    ULL r; asm("mov.b64 %0, {%1, %2};" : "=l"(r) : "f"(x), "f"(y)); return r;
}
__device__ __forceinline__ void unpack2(ULL v, float& x, float& y) {
    asm("mov.b64 {%0, %1}, %2;" : "=f"(x), "=f"(y) : "l"(v));
}
__device__ __forceinline__ void fma2(ULL& d, ULL a, ULL b) {
    asm("fma.rn.f32x2 %0, %1, %2, %0;" : "+l"(d) : "l"(a), "l"(b));
}
__device__ __forceinline__ uint32_t smem_u32(const void* p) {
    uint32_t a;
    asm("{ .reg .u64 t; cvta.to.shared.u64 t, %1; cvt.u32.u64 %0, t; }" : "=r"(a) : "l"(p));
    return a;
}
__device__ __forceinline__ void cp_async16(uint32_t dst, const void* src) {
    asm volatile("cp.async.cg.shared.global [%0], [%1], 16;\n" :: "r"(dst), "l"(src));
}

// ---------------- prep: transpose + pad weights ----------------
struct Params { const float* in[32]; float* out; int out_size; };

__global__ void prep_kernel(Params P) {
    const int L = blockIdx.x;
    const int CIN  = c_layers[L][2], COUT = c_layers[L][3];
    const int KPAD = c_layers[L][4], CW   = c_layers[L][5];
    const int woff = c_layers[L][6], boff = c_layers[L][7];
    const float* W = P.in[c_layers[L][0]];
    const float* b = P.in[c_layers[L][1]];
    for (int e = threadIdx.x; e < KPAD * CW; e += blockDim.x) {
        int k = e / CW, c = e - (e / CW) * CW;
        float v = (k < CIN && c < COUT) ? W[c * CIN + k] : 0.f;
        g_Wt[woff + e] = v;
    }
    for (int c = threadIdx.x; c < CW; c += blockDim.x)
        g_bias[boff + c] = (c < COUT) ? b[c] : 0.f;
}

// ---------------- channel ownership (bank-conflict-free quads) ----------------
template<int MT>
__device__ __forceinline__ int chan(int ty, int m) {
    if constexpr (MT == 8) return (m < 4) ? ty * 4 + m : 128 + ty * 4 + (m - 4);
    else if constexpr (MT == 6) return (m < 4) ? ty * 4 + m : 128 + ty * 2 + (m - 4);
    else if constexpr (MT == 4) return ty * 4 + m;
    else if constexpr (MT == 2) return ty * 2 + m;
    else return ty;
}

template<int MT>
__device__ __forceinline__ void load_wf(const float* Wrow, int ty, float* wf) {
    if constexpr (MT == 8) {
        float4 a = *reinterpret_cast<const float4*>(Wrow + ty * 4);
        float4 b = *reinterpret_cast<const float4*>(Wrow + 128 + ty * 4);
        wf[0] = a.x; wf[1] = a.y; wf[2] = a.z; wf[3] = a.w;
        wf[4] = b.x; wf[5] = b.y; wf[6] = b.z; wf[7] = b.w;
    } else if constexpr (MT == 6) {
        float4 a = *reinterpret_cast<const float4*>(Wrow + ty * 4);
        float2 b = *reinterpret_cast<const float2*>(Wrow + 128 + ty * 2);
        wf[0] = a.x; wf[1] = a.y; wf[2] = a.z; wf[3] = a.w;
        wf[4] = b.x; wf[5] = b.y;
    } else if constexpr (MT == 4) {
        float4 a = *reinterpret_cast<const float4*>(Wrow + ty * 4);
        wf[0] = a.x; wf[1] = a.y; wf[2] = a.z; wf[3] = a.w;
    } else if constexpr (MT == 2) {
        float2 a = *reinterpret_cast<const float2*>(Wrow + ty * 2);
        wf[0] = a.x; wf[1] = a.y;
    } else {
        wf[0] = Wrow[ty];
    }
}

// ---------------- fused 1x1-conv layer (in-place capable) ----------------
// OUT[c][t] = (RES? OUT[c][t]:0) + bias[c] + sum_k W[c][k]*(PRE? relu(IN[k][t]) : IN[k][t])
// 256 threads: 32 channel-groups (MT ch) x 8 token-groups (8 tokens)
// STAGE: OUT overlaps IN -> barrier between last read and writeback.
template<int CW, int KPAD, int KBT, bool PRE, bool POST, bool RES, bool STAGE>
__device__ __noinline__ void conv_layer(const float* __restrict__ Wt,
                                        const float* __restrict__ bias,
                                        const float* __restrict__ IN,
                                        float* __restrict__ OUT,
                                        float* __restrict__ Ws, int tid)
{
    constexpr int MT = CW / 32;
    constexpr int NK = KPAD / KBT;
    constexpr int CHUNKF = KBT * CW;
    static_assert(CHUNKF <= WBUFF, "chunk too big");

    const int tx = tid & 7;
    const int ty = tid >> 3;      // 0..31
    const int j0 = tx * 8;

    ULL acc[4][MT];
#pragma unroll
    for (int t = 0; t < 4; t++)
#pragma unroll
        for (int m = 0; m < MT; m++) acc[t][m] = 0ull;

    __syncthreads();   // prev-layer writes visible; Ws free

    // stage chunk 0 (linear memcpy)
    {
        const float4* src = reinterpret_cast<const float4*>(Wt);
        float4* dst = reinterpret_cast<float4*>(Ws);
#pragma unroll
        for (int i = tid; i < CHUNKF / 4; i += THREADS)
            cp_async16(smem_u32(dst + i), src + i);
        asm volatile("cp.async.commit_group;\n" ::: "memory");
    }

    for (int kb = 0; kb < NK; kb++) {
        asm volatile("cp.async.wait_group 0;\n" ::: "memory");
        __syncthreads();
        if (kb + 1 < NK) {
            const float4* src = reinterpret_cast<const float4*>(Wt + (kb + 1) * CHUNKF);
            float4* dst = reinterpret_cast<float4*>(Ws + ((kb + 1) & 1) * WBUFF);
#pragma unroll
            for (int i = tid; i < CHUNKF / 4; i += THREADS)
                cp_async16(smem_u32(dst + i), src + i);
            asm volatile("cp.async.commit_group;\n" ::: "memory");
        }

        const float* Wk  = Ws + (kb & 1) * WBUFF;
        const float* inb = IN + kb * KBT * LDA + j0;

#pragma unroll 8
        for (int kk = 0; kk < KBT; kk++) {
            float4 va = *reinterpret_cast<const float4*>(inb + kk * LDA);
            float4 vb = *reinterpret_cast<const float4*>(inb + kk * LDA + 4);
            if (PRE) {
                va.x = fmaxf(va.x, 0.f); va.y = fmaxf(va.y, 0.f);
                va.z = fmaxf(va.z, 0.f); va.w = fmaxf(va.w, 0.f);
                vb.x = fmaxf(vb.x, 0.f); vb.y = fmaxf(vb.y, 0.f);
                vb.z = fmaxf(vb.z, 0.f); vb.w = fmaxf(vb.w, 0.f);
            }
            ULL t0 = pack2(va.x, va.y), t1 = pack2(va.z, va.w);
            ULL t2 = pack2(vb.x, vb.y), t3 = pack2(vb.z, vb.w);
            float wf[MT];
            load_wf<MT>(Wk + kk * CW, ty, wf);
#pragma unroll
            for (int m = 0; m < MT; m++) {
                ULL wd = pack2(wf[m], wf[m]);
                fma2(acc[0][m], wd, t0);
                fma2(acc[1][m], wd, t1);
                fma2(acc[2][m], wd, t2);
                fma2(acc[3][m], wd, t3);
            }
        }
    }

    // in-place staging barrier: all threads finished reading IN
    if (STAGE) __syncthreads();

    // epilogue: thread exclusively owns (ch, 8-token) slots of OUT
#pragma unroll
    for (int m = 0; m < MT; m++) {
        float bv = __ldg(bias + chan<MT>(ty, m));
        float r[8];
        unpack2(acc[0][m], r[0], r[1]);
        unpack2(acc[1][m], r[2], r[3]);
        unpack2(acc[2][m], r[4], r[5]);
        unpack2(acc[3][m], r[6], r[7]);
        float* op = OUT + chan<MT>(ty, m) * LDA + j0;
        float4 o0, o1;
        o0.x = r[0] + bv; o0.y = r[1] + bv;
        o0.z = r[2] + bv; o0.w = r[3] + bv;
        o1.x = r[4] + bv; o1.y = r[5] + bv;
        o1.z = r[6] + bv; o1.w = r[7] + bv;
        if (RES) {
            float4 e0 = *reinterpret_cast<float4*>(op);
            float4 e1 = *reinterpret_cast<float4*>(op + 4);
            o0.x += e0.x; o0.y += e0.y; o0.z += e0.z; o0.w += e0.w;
            o1.x += e1.x; o1.y += e1.y; o1.z += e1.z; o1.w += e1.w;
        }
        if (POST) {
            o0.x = fmaxf(o0.x, 0.f); o0.y = fmaxf(o0.y, 0.f);
            o0.z = fmaxf(o0.z, 0.f); o0.w = fmaxf(o0.w, 0.f);
            o1.x = fmaxf(o1.x, 0.f); o1.y = fmaxf(o1.y, 0.f);
            o1.z = fmaxf(o1.z, 0.f); o1.w = fmaxf(o1.w, 0.f);
        }
        *reinterpret_cast<float4*>(op)     = o0;
        *reinterpret_cast<float4*>(op + 4) = o1;
    }
}

#define LCONV(L, CW, KPAD, KBT, PRE, POST, RES, STAGE, INB, OUTB) \
    conv_layer<CW, KPAD, KBT, PRE, POST, RES, STAGE>(g_Wt + c_layers[L][6], g_bias + c_layers[L][7], INB, OUTB, Ws, tid)

// ---------------- main fused kernel ----------------
__global__ void __launch_bounds__(THREADS, 2) vqvae_kernel(Params P)
{
    extern __shared__ float sm[];
    float* A    = sm + SM_A;             // 288 rows x LDA
    float* T32  = A + 256 * LDA;         // resblock intermediate rows 256..287
    float* Ws   = sm + SM_W;
    float* enp  = sm + SM_AUX;           // [256]
    float* en   = enp + 256;             // [64]
    float* wsum = en + 64;               // [8]

    const int tid = threadIdx.x;
    const int n0  = blockIdx.x * TILE;

    // ---- load x tile: [tok][c] -> [c][tok]; zero-pad rows 165..175 ----
    const float* x = P.in[0];
    for (int idx = tid; idx < 176 * TILE; idx += THREADS) {
        int c = idx % 176;
        int j = idx / 176;
        A[c * LDA + j] = (c < CINN) ? x[(n0 + j) * CINN + c] : 0.f;
    }

    // ---- encoder (all in-place in A; resblock mids in T32) ----
    LCONV(0, 128, 176, 16, false, true,  false, true,  A,   A  );
    LCONV(1, 256, 128, 16, false, true,  false, true,  A,   A  );
    LCONV(2, 256, 256, 16, false, false, false, true,  A,   A  );
    LCONV(3,  32, 256, 128, true, true,  false, false, A,   T32);
    LCONV(4, 256,  32, 16, false, false, true,  false, T32, A  );
    LCONV(5,  32, 256, 128, true, true,  false, false, A,   T32);
    LCONV(6, 256,  32, 16, false, false, true,  false, T32, A  );
    LCONV(7,  64, 256, 64, true,  false, false, true,  A,   A  );   // z -> rows 0..63

    // ---- vector quantize (z in A rows 0..63) ----
    {
        const float* embed = P.in[17];
        float* Es = Ws;                 // [64 d][64 codes] = 16KB
        const int j = tid >> 2;         // token 0..63
        const int q = tid & 3;          // code 16-chunk within 64-code block
        float best = 3.4e38f; int bidx = 0;

        for (int cb = 0; cb < 8; cb++) {
            __syncthreads();
            float sq = 0.f;
#pragma unroll
            for (int i = 0; i < 16; i++) {
                int idx = i * THREADS + tid;
                int kk = idx & 63, d = idx >> 6;
                float v = __ldg(embed + d * NEMB + cb * 64 + kk);
                Es[d * 64 + kk] = v;
                sq += v * v;            // all iterations share kk = tid&63
            }
            enp[tid] = sq;
            __syncthreads();
            if (tid < 64)
                en[tid] = enp[tid] + enp[tid + 64] + enp[tid + 128] + enp[tid + 192];
            __syncthreads();

            ULL dot[8];
#pragma unroll
            for (int g = 0; g < 8; g++) dot[g] = 0ull;
#pragma unroll 8
            for (int d = 0; d < EDIM; d++) {
                float z = A[d * LDA + j];
                ULL z2 = pack2(z, z);
                const ulonglong2* er = reinterpret_cast<const ulonglong2*>(Es + d * 64 + q * 16);
                ulonglong2 e0 = er[0], e1 = er[1], e2 = er[2], e3 = er[3];
                fma2(dot[0], z2, e0.x); fma2(dot[1], z2, e0.y);
                fma2(dot[2], z2, e1.x); fma2(dot[3], z2, e1.y);
                fma2(dot[4], z2, e2.x); fma2(dot[5], z2, e2.y);
                fma2(dot[6], z2, e3.x); fma2(dot[7], z2, e3.y);
            }
#pragma unroll
            for (int g = 0; g < 8; g++) {
                float d0, d1; unpack2(dot[g], d0, d1);
                int kbv = cb * 64 + q * 16 + 2 * g;
                float s0 = en[q * 16 + 2 * g]     - 2.f * d0;
                float s1 = en[q * 16 + 2 * g + 1] - 2.f * d1;
                if (s0 < best) { best = s0; bidx = kbv; }
                if (s1 < best) { best = s1; bidx = kbv + 1; }
            }
        }
        // argmin across 4 lanes of this token (tie -> lower index)
#pragma unroll
        for (int off = 1; off < 4; off <<= 1) {
            float ob = __shfl_xor_sync(0xffffffffu, best, off);
            int   oi = __shfl_xor_sync(0xffffffffu, bidx, off);
            if (ob < best || (ob == best && oi < bidx)) { best = ob; bidx = oi; }
        }
        // gather codebook vector into A (in place), accumulate diff partial
        float dsum = 0.f;
#pragma unroll
        for (int dd = 0; dd < 16; dd++) {
            int d = q * 16 + dd;
            float e = __ldg(embed + d * NEMB + bidx);
            float z = A[d * LDA + j];
            A[d * LDA + j] = e;
            float df = e - z;
            dsum += df * df;
        }
#pragma unroll
        for (int off = 16; off > 0; off >>= 1)
            dsum += __shfl_xor_sync(0xffffffffu, dsum, off);
        if ((tid & 31) == 0) wsum[tid >> 5] = dsum;
        __syncthreads();
        if (tid == 0) {
            float s = 0.f;
#pragma unroll
            for (int w = 0; w < 8; w++) s += wsum[w];
            g_part[blockIdx.x] = s;
        }
    }

    // ---- decoder ----
    LCONV( 8, 256,  64, 16, false, false, false, true,  A,   A  );
    LCONV( 9,  32, 256, 128, true, true,  false, false, A,   T32);
    LCONV(10, 256,  32, 16, false, false, true,  false, T32, A  );
    LCONV(11,  32, 256, 128, true, true,  false, false, A,   T32);
    LCONV(12, 256,  32, 16, false, false, true,  false, T32, A  );
    LCONV(13, 128, 256, 32, true,  true,  false, true,  A,   A  );
    LCONV(14, 192, 128, 16, false, false, false, true,  A,   A  );
    __syncthreads();

    // ---- store output tile: [c][tok] -> [tok][c] ----
    for (int idx = tid; idx < CINN * TILE; idx += THREADS) {
        int j = idx / CINN;
        int c = idx - j * CINN;
        P.out[(n0 + j) * CINN + c] = A[c * LDA + j];
    }

    // ---- last-block finalize of diff ----
    __threadfence();
    __shared__ unsigned int is_last;
    if (tid == 0) is_last = (atomicAdd(&g_count, 1u) == NBLK - 1) ? 1u : 0u;
    __syncthreads();
    if (is_last) {
        float s = 0.f;
        for (int i = tid; i < NBLK; i += THREADS) s += g_part[i];
#pragma unroll
        for (int off = 16; off > 0; off >>= 1)
            s += __shfl_xor_sync(0xffffffffu, s, off);
        if ((tid & 31) == 0) wsum[tid >> 5] = s;
        __syncthreads();
        if (tid == 0) {
            float t = 0.f;
#pragma unroll
            for (int w = 0; w < 8; w++) t += wsum[w];
            if (P.out_size > DEC_ELEMS)
                P.out[DEC_ELEMS] = t * (1.0f / 8388608.0f);  // mean over N*EDIM
            g_count = 0u;   // reset for next graph replay
        }
    }
}

// ---------------- launch ----------------
extern "C" void kernel_launch(void* const* d_in, const int* in_sizes, int n_in,
                              void* d_out, int out_size)
{
    (void)in_sizes; (void)n_in;
    Params P;
    for (int i = 0; i < 32; i++) P.in[i] = (const float*)d_in[i];
    P.out = (float*)d_out;
    P.out_size = out_size;

    static bool attr_set = false;
    if (!attr_set) {
        cudaFuncSetAttribute(vqvae_kernel, cudaFuncAttributeMaxDynamicSharedMemorySize, SMEM_BYTES);
        attr_set = true;
    }
    prep_kernel<<<15, 256>>>(P);
    vqvae_kernel<<<NBLK, THREADS, SMEM_BYTES>>>(P);
}

// round 11
// speedup vs baseline: 1.3321x; 1.3321x over previous
#include <cuda_runtime.h>
#include <cstdint>

// ---------------- problem constants ----------------
#define BN   32
#define TN   4096
#define CINN 165
#define EDIM 64
#define NEMB 512
#define NTOK (BN*TN)          // 131072
#define TILE 32               // tokens per CTA
#define NBLK (NTOK/TILE)      // 4096
#define LDA  36               // padded token-row stride (floats)
#define DEC_ELEMS (NTOK*CINN) // 21626880
#define THREADS 128

// shared layout (floats): in-place activation buffer A[288 rows] + VQ scratch
#define AROWS  288
#define SM_A   0
#define SM_ES  (AROWS*LDA)          // 10368
#define SM_AUX (SM_ES + 4096)       // 14464 (Es = 64x64 codebook tile)
#define SM_FLOATS (SM_AUX + 128 + 64 + 8)
#define SMEM_BYTES (SM_FLOATS*4)    // ~58.7 KB -> 3 CTAs/SM (reg-limited)

typedef unsigned long long ULL;

// transposed+padded weights and bias, built once per launch by prep_kernel
__device__ float g_Wt[276480];
__device__ float g_bias[2432];
__device__ float g_part[NBLK];
__device__ unsigned int g_count;

// layer metadata: {w_in_idx, b_in_idx, CIN, COUT, KPAD, CW, woff, boff}
__constant__ int c_layers[15][8] = {
    { 1,  2, 165, 128, 176, 128,      0,    0},
    { 3,  4, 128, 256, 128, 256,  22528,  128},
    { 5,  6, 256, 256, 256, 256,  55296,  384},
    { 7,  8, 256,  32, 256,  32, 120832,  640},
    { 9, 10,  32, 256,  32, 256, 129024,  672},
    {11, 12, 256,  32, 256,  32, 137216,  928},
    {13, 14,  32, 256,  32, 256, 145408,  960},
    {15, 16, 256,  64, 256,  64, 153600, 1216},
    {18, 19,  64, 256,  64, 256, 169984, 1280},
    {20, 21, 256,  32, 256,  32, 186368, 1536},
    {22, 23,  32, 256,  32, 256, 194560, 1568},
    {24, 25, 256,  32, 256,  32, 202752, 1824},
    {26, 27,  32, 256,  32, 256, 210944, 1856},
    {28, 29, 256, 128, 256, 128, 219136, 2112},
    {30, 31, 128, 165, 128, 192, 251904, 2240},
};

// ---------------- f32x2 helpers ----------------
__device__ __forceinline__ ULL pack2(float x, float y) {
    ULL r; asm("mov.b64 %0, {%1, %2};" : "=l"(r) : "f"(x), "f"(y)); return r;
}
__device__ __forceinline__ void unpack2(ULL v, float& x, float& y) {
    asm("mov.b64 {%0, %1}, %2;" : "=f"(x), "=f"(y) : "l"(v));
}
__device__ __forceinline__ void fma2(ULL& d, ULL a, ULL b) {
    asm("fma.rn.f32x2 %0, %1, %2, %0;" : "+l"(d) : "l"(a), "l"(b));
}

// ---------------- prep: transpose + pad weights ----------------
struct Params { const float* in[32]; float* out; int out_size; };

__global__ void prep_kernel(Params P) {
    const int L = blockIdx.x;
    const int CIN  = c_layers[L][2], COUT = c_layers[L][3];
    const int KPAD = c_layers[L][4], CW   = c_layers[L][5];
    const int woff = c_layers[L][6], boff = c_layers[L][7];
    const float* W = P.in[c_layers[L][0]];
    const float* b = P.in[c_layers[L][1]];
    for (int e = threadIdx.x; e < KPAD * CW; e += blockDim.x) {
        int k = e / CW, c = e - (e / CW) * CW;
        float v = (k < CIN && c < COUT) ? W[c * CIN + k] : 0.f;
        g_Wt[woff + e] = v;
    }
    for (int c = threadIdx.x; c < CW; c += blockDim.x)
        g_bias[boff + c] = (c < COUT) ? b[c] : 0.f;
}

// ---------------- channel ownership (contiguous quads) ----------------
template<int MT>
__device__ __forceinline__ int chan(int ty, int m) {
    if constexpr (MT == 8) return (m < 4) ? ty * 4 + m : 128 + ty * 4 + (m - 4);
    else if constexpr (MT == 6) return (m < 4) ? ty * 4 + m : 128 + ty * 2 + (m - 4);
    else if constexpr (MT == 4) return ty * 4 + m;
    else if constexpr (MT == 2) return ty * 2 + m;
    else return ty;
}

// weights straight from L2 (read-only, warp-coalesced 128B lines)
template<int MT>
__device__ __forceinline__ void ldg_wf(const float* Wrow, int ty, float* wf) {
    if constexpr (MT == 8) {
        float4 a = __ldg(reinterpret_cast<const float4*>(Wrow + ty * 4));
        float4 b = __ldg(reinterpret_cast<const float4*>(Wrow + 128 + ty * 4));
        wf[0] = a.x; wf[1] = a.y; wf[2] = a.z; wf[3] = a.w;
        wf[4] = b.x; wf[5] = b.y; wf[6] = b.z; wf[7] = b.w;
    } else if constexpr (MT == 6) {
        float4 a = __ldg(reinterpret_cast<const float4*>(Wrow + ty * 4));
        float2 b = __ldg(reinterpret_cast<const float2*>(Wrow + 128 + ty * 2));
        wf[0] = a.x; wf[1] = a.y; wf[2] = a.z; wf[3] = a.w;
        wf[4] = b.x; wf[5] = b.y;
    } else if constexpr (MT == 4) {
        float4 a = __ldg(reinterpret_cast<const float4*>(Wrow + ty * 4));
        wf[0] = a.x; wf[1] = a.y; wf[2] = a.z; wf[3] = a.w;
    } else if constexpr (MT == 2) {
        float2 a = __ldg(reinterpret_cast<const float2*>(Wrow + ty * 2));
        wf[0] = a.x; wf[1] = a.y;
    } else {
        wf[0] = __ldg(Wrow + ty);
    }
}

// ---------------- fused 1x1-conv layer (in-place, weights from L2) ----------------
// OUT[c][t] = (RES? OUT[c][t]:0) + bias[c] + sum_k W[c][k]*(PRE? relu(IN[k][t]) : IN[k][t])
// 128 threads: 32 channel-groups (MT ch) x 4 token-groups (8 tokens)
// STAGE: OUT overlaps IN -> barrier between last read and writeback.
template<int CW, int KPAD, bool PRE, bool POST, bool RES, bool STAGE>
__device__ __noinline__ void conv_layer(const float* __restrict__ Wt,
                                        const float* __restrict__ bias,
                                        const float* __restrict__ IN,
                                        float* __restrict__ OUT, int tid)
{
    constexpr int MT = CW / 32;

    const int tx = tid & 3;
    const int ty = tid >> 2;      // 0..31
    const int j0 = tx * 8;

    float bv[MT];
#pragma unroll
    for (int m = 0; m < MT; m++) bv[m] = __ldg(bias + chan<MT>(ty, m));

    ULL acc[4][MT];
#pragma unroll
    for (int t = 0; t < 4; t++)
#pragma unroll
        for (int m = 0; m < MT; m++) acc[t][m] = 0ull;

    __syncthreads();   // prev-layer writes visible

    const float* inb = IN + j0;
    const float* wrow = Wt + ty * 0;   // base; indexed per k below

#pragma unroll 8
    for (int k = 0; k < KPAD; k++) {
        float4 va = *reinterpret_cast<const float4*>(inb + k * LDA);
        float4 vb = *reinterpret_cast<const float4*>(inb + k * LDA + 4);
        if (PRE) {
            va.x = fmaxf(va.x, 0.f); va.y = fmaxf(va.y, 0.f);
            va.z = fmaxf(va.z, 0.f); va.w = fmaxf(va.w, 0.f);
            vb.x = fmaxf(vb.x, 0.f); vb.y = fmaxf(vb.y, 0.f);
            vb.z = fmaxf(vb.z, 0.f); vb.w = fmaxf(vb.w, 0.f);
        }
        ULL t0 = pack2(va.x, va.y), t1 = pack2(va.z, va.w);
        ULL t2 = pack2(vb.x, vb.y), t3 = pack2(vb.z, vb.w);
        float wf[MT];
        ldg_wf<MT>(Wt + k * CW, ty, wf);
#pragma unroll
        for (int m = 0; m < MT; m++) {
            ULL wd = pack2(wf[m], wf[m]);
            fma2(acc[0][m], wd, t0);
            fma2(acc[1][m], wd, t1);
            fma2(acc[2][m], wd, t2);
            fma2(acc[3][m], wd, t3);
        }
    }
    (void)wrow;

    // in-place staging barrier: all threads finished reading IN
    if (STAGE) __syncthreads();

    // epilogue: thread exclusively owns (ch, 8-token) slots of OUT
#pragma unroll
    for (int m = 0; m < MT; m++) {
        float r[8];
        unpack2(acc[0][m], r[0], r[1]);
        unpack2(acc[1][m], r[2], r[3]);
        unpack2(acc[2][m], r[4], r[5]);
        unpack2(acc[3][m], r[6], r[7]);
        float* op = OUT + chan<MT>(ty, m) * LDA + j0;
        float4 o0, o1;
        o0.x = r[0] + bv[m]; o0.y = r[1] + bv[m];
        o0.z = r[2] + bv[m]; o0.w = r[3] + bv[m];
        o1.x = r[4] + bv[m]; o1.y = r[5] + bv[m];
        o1.z = r[6] + bv[m]; o1.w = r[7] + bv[m];
        if (RES) {
            float4 e0 = *reinterpret_cast<float4*>(op);
            float4 e1 = *reinterpret_cast<float4*>(op + 4);
            o0.x += e0.x; o0.y += e0.y; o0.z += e0.z; o0.w += e0.w;
            o1.x += e1.x; o1.y += e1.y; o1.z += e1.z; o1.w += e1.w;
        }
        if (POST) {
            o0.x = fmaxf(o0.x, 0.f); o0.y = fmaxf(o0.y, 0.f);
            o0.z = fmaxf(o0.z, 0.f); o0.w = fmaxf(o0.w, 0.f);
            o1.x = fmaxf(o1.x, 0.f); o1.y = fmaxf(o1.y, 0.f);
            o1.z = fmaxf(o1.z, 0.f); o1.w = fmaxf(o1.w, 0.f);
        }
        *reinterpret_cast<float4*>(op)     = o0;
        *reinterpret_cast<float4*>(op + 4) = o1;
    }
}

#define LCONV(L, CW, KPAD, PRE, POST, RES, STAGE, INB, OUTB) \
    conv_layer<CW, KPAD, PRE, POST, RES, STAGE>(g_Wt + c_layers[L][6], g_bias + c_layers[L][7], INB, OUTB, tid)

// ---------------- main fused kernel ----------------
__global__ void __launch_bounds__(THREADS, 3) vqvae_kernel(Params P)
{
    extern __shared__ float sm[];
    float* A    = sm + SM_A;             // 288 rows x LDA
    float* T32  = A + 256 * LDA;         // resblock intermediate rows 256..287
    float* Es   = sm + SM_ES;            // [64 d][64 codes] = 16KB
    float* enp  = sm + SM_AUX;           // [128]
    float* en   = enp + 128;             // [64]
    float* wsum = en + 64;               // [8]

    const int tid = threadIdx.x;
    const int n0  = blockIdx.x * TILE;

    // ---- load x tile: [tok][c] -> [c][tok]; zero-pad rows 165..175 ----
    const float* x = P.in[0];
    for (int idx = tid; idx < 176 * TILE; idx += THREADS) {
        int c = idx % 176;
        int j = idx / 176;
        A[c * LDA + j] = (c < CINN) ? x[(n0 + j) * CINN + c] : 0.f;
    }

    // ---- encoder (all in-place in A; resblock mids in T32) ----
    LCONV(0, 128, 176, false, true,  false, true,  A,   A  );
    LCONV(1, 256, 128, false, true,  false, true,  A,   A  );
    LCONV(2, 256, 256, false, false, false, true,  A,   A  );
    LCONV(3,  32, 256, true,  true,  false, false, A,   T32);
    LCONV(4, 256,  32, false, false, true,  false, T32, A  );
    LCONV(5,  32, 256, true,  true,  false, false, A,   T32);
    LCONV(6, 256,  32, false, false, true,  false, T32, A  );
    LCONV(7,  64, 256, true,  false, false, true,  A,   A  );   // z -> rows 0..63

    // ---- vector quantize (z in A rows 0..63) ----
    {
        const float* embed = P.in[17];
        const int j = tid >> 2;         // token 0..31
        const int q = tid & 3;          // code 16-chunk within 64-code block
        float best = 3.4e38f; int bidx = 0;

        for (int cb = 0; cb < 8; cb++) {
            __syncthreads();
            float sq = 0.f;
#pragma unroll
            for (int i = 0; i < 32; i++) {
                int idx = i * THREADS + tid;
                int kk = idx & 63, d = idx >> 6;
                float v = __ldg(embed + d * NEMB + cb * 64 + kk);
                Es[d * 64 + kk] = v;
                sq += v * v;            // all iterations share kk = tid&63
            }
            enp[tid] = sq;
            __syncthreads();
            if (tid < 64) en[tid] = enp[tid] + enp[tid + 64];
            __syncthreads();

            ULL dot[8];
#pragma unroll
            for (int g = 0; g < 8; g++) dot[g] = 0ull;
#pragma unroll 8
            for (int d = 0; d < EDIM; d++) {
                float z = A[d * LDA + j];
                ULL z2 = pack2(z, z);
                const ulonglong2* er = reinterpret_cast<const ulonglong2*>(Es + d * 64 + q * 16);
                ulonglong2 e0 = er[0], e1 = er[1], e2 = er[2], e3 = er[3];
                fma2(dot[0], z2, e0.x); fma2(dot[1], z2, e0.y);
                fma2(dot[2], z2, e1.x); fma2(dot[3], z2, e1.y);
                fma2(dot[4], z2, e2.x); fma2(dot[5], z2, e2.y);
                fma2(dot[6], z2, e3.x); fma2(dot[7], z2, e3.y);
            }
#pragma unroll
            for (int g = 0; g < 8; g++) {
                float d0, d1; unpack2(dot[g], d0, d1);
                int kbv = cb * 64 + q * 16 + 2 * g;
                float s0 = en[q * 16 + 2 * g]     - 2.f * d0;
                float s1 = en[q * 16 + 2 * g + 1] - 2.f * d1;
                if (s0 < best) { best = s0; bidx = kbv; }
                if (s1 < best) { best = s1; bidx = kbv + 1; }
            }
        }
        // argmin across 4 lanes of this token (tie -> lower index)
#pragma unroll
        for (int off = 1; off < 4; off <<= 1) {
            float ob = __shfl_xor_sync(0xffffffffu, best, off);
            int   oi = __shfl_xor_sync(0xffffffffu, bidx, off);
            if (ob < best || (ob == best && oi < bidx)) { best = ob; bidx = oi; }
        }
        // gather codebook vector into A (in place), accumulate diff partial
        float dsum = 0.f;
#pragma unroll
        for (int dd = 0; dd < 16; dd++) {
            int d = q * 16 + dd;
            float e = __ldg(embed + d * NEMB + bidx);
            float z = A[d * LDA + j];
            A[d * LDA + j] = e;
            float df = e - z;
            dsum += df * df;
        }
#pragma unroll
        for (int off = 16; off > 0; off >>= 1)
            dsum += __shfl_xor_sync(0xffffffffu, dsum, off);
        if ((tid & 31) == 0) wsum[tid >> 5] = dsum;
        __syncthreads();
        if (tid == 0)
            g_part[blockIdx.x] = wsum[0] + wsum[1] + wsum[2] + wsum[3];
    }

    // ---- decoder ----
    LCONV( 8, 256,  64, false, false, false, true,  A,   A  );
    LCONV( 9,  32, 256, true,  true,  false, false, A,   T32);
    LCONV(10, 256,  32, false, false, true,  false, T32, A  );
    LCONV(11,  32, 256, true,  true,  false, false, A,   T32);
    LCONV(12, 256,  32, false, false, true,  false, T32, A  );
    LCONV(13, 128, 256, true,  true,  false, true,  A,   A  );
    LCONV(14, 192, 128, false, false, false, true,  A,   A  );
    __syncthreads();

    // ---- store output tile: [c][tok] -> [tok][c] ----
    for (int idx = tid; idx < CINN * TILE; idx += THREADS) {
        int j = idx / CINN;
        int c = idx - j * CINN;
        P.out[(n0 + j) * CINN + c] = A[c * LDA + j];
    }

    // ---- last-block finalize of diff ----
    __threadfence();
    __shared__ unsigned int is_last;
    if (tid == 0) is_last = (atomicAdd(&g_count, 1u) == NBLK - 1) ? 1u : 0u;
    __syncthreads();
    if (is_last) {
        float s = 0.f;
        for (int i = tid; i < NBLK; i += THREADS) s += g_part[i];
#pragma unroll
        for (int off = 16; off > 0; off >>= 1)
            s += __shfl_xor_sync(0xffffffffu, s, off);
        if ((tid & 31) == 0) wsum[tid >> 5] = s;
        __syncthreads();
        if (tid == 0) {
            float t = wsum[0] + wsum[1] + wsum[2] + wsum[3];
            if (P.out_size > DEC_ELEMS)
                P.out[DEC_ELEMS] = t * (1.0f / 8388608.0f);  // mean over N*EDIM
            g_count = 0u;   // reset for next graph replay
        }
    }
}

// ---------------- launch ----------------
extern "C" void kernel_launch(void* const* d_in, const int* in_sizes, int n_in,
                              void* d_out, int out_size)
{
    (void)in_sizes; (void)n_in;
    Params P;
    for (int i = 0; i < 32; i++) P.in[i] = (const float*)d_in[i];
    P.out = (float*)d_out;
    P.out_size = out_size;

    static bool attr_set = false;
    if (!attr_set) {
        cudaFuncSetAttribute(vqvae_kernel, cudaFuncAttributeMaxDynamicSharedMemorySize, SMEM_BYTES);
        attr_set = true;
    }
    prep_kernel<<<15, 256>>>(P);
    vqvae_kernel<<<NBLK, THREADS, SMEM_BYTES>>>(P);
}

// round 12
// speedup vs baseline: 1.3680x; 1.0270x over previous
#include <cuda_runtime.h>
#include <cstdint>

// ---------------- problem constants ----------------
#define BN   32
#define TN   4096
#define CINN 165
#define EDIM 64
#define NEMB 512
#define NTOK (BN*TN)          // 131072
#define TILE 32               // tokens per CTA
#define NBLK (NTOK/TILE)      // 4096
#define LDA  36               // padded token-row stride (floats)
#define DEC_ELEMS (NTOK*CINN) // 21626880
#define THREADS 128

// shared layout (floats): in-place activation buffer A[288 rows] + weight ring
#define AROWS  288
#define SM_A   0
#define SM_W   (AROWS*LDA)          // 10368
#define WBUFF  4096                 // floats per weight buffer (KBT*CW <= 4096)
#define SM_AUX (SM_W + 2*WBUFF)     // 18560
#define SM_FLOATS (SM_AUX + 16)
#define SMEM_BYTES (SM_FLOATS*4)    // ~74.3 KB -> 3 CTAs/SM

typedef unsigned long long ULL;

// transposed+padded weights, bias, codebook norms: built by prep_kernel
__device__ float g_Wt[276480];
__device__ float g_bias[2432];
__device__ float g_enorm[NEMB];
__device__ float g_part[NBLK];
__device__ unsigned int g_count;

// layer metadata: {w_in_idx, b_in_idx, CIN, COUT, KPAD, CW, woff, boff}
__constant__ int c_layers[15][8] = {
    { 1,  2, 165, 128, 176, 128,      0,    0},
    { 3,  4, 128, 256, 128, 256,  22528,  128},
    { 5,  6, 256, 256, 256, 256,  55296,  384},
    { 7,  8, 256,  32, 256,  32, 120832,  640},
    { 9, 10,  32, 256,  32, 256, 129024,  672},
    {11, 12, 256,  32, 256,  32, 137216,  928},
    {13, 14,  32, 256,  32, 256, 145408,  960},
    {15, 16, 256,  64, 256,  64, 153600, 1216},
    {18, 19,  64, 256,  64, 256, 169984, 1280},
    {20, 21, 256,  32, 256,  32, 186368, 1536},
    {22, 23,  32, 256,  32, 256, 194560, 1568},
    {24, 25, 256,  32, 256,  32, 202752, 1824},
    {26, 27,  32, 256,  32, 256, 210944, 1856},
    {28, 29, 256, 128, 256, 128, 219136, 2112},
    {30, 31, 128, 165, 128, 192, 251904, 2240},
};

// ---------------- f32x2 helpers ----------------
__device__ __forceinline__ ULL pack2(float x, float y) {
    ULL r; asm("mov.b64 %0, {%1, %2};" : "=l"(r) : "f"(x), "f"(y)); return r;
}
__device__ __forceinline__ void unpack2(ULL v, float& x, float& y) {
    asm("mov.b64 {%0, %1}, %2;" : "=f"(x), "=f"(y) : "l"(v));
}
__device__ __forceinline__ void fma2(ULL& d, ULL a, ULL b) {
    asm("fma.rn.f32x2 %0, %1, %2, %0;" : "+l"(d) : "l"(a), "l"(b));
}
__device__ __forceinline__ uint32_t smem_u32(const void* p) {
    uint32_t a;
    asm("{ .reg .u64 t; cvta.to.shared.u64 t, %1; cvt.u32.u64 %0, t; }" : "=r"(a) : "l"(p));
    return a;
}
__device__ __forceinline__ void cp_async16(uint32_t dst, const void* src) {
    asm volatile("cp.async.cg.shared.global [%0], [%1], 16;\n" :: "r"(dst), "l"(src));
}

// ---------------- prep: transpose + pad weights, codebook norms ----------------
struct Params { const float* in[32]; float* out; int out_size; };

__global__ void prep_kernel(Params P) {
    const int L = blockIdx.x;
    if (L == 15) {   // codebook norms
        const float* embed = P.in[17];
        for (int k = threadIdx.x; k < NEMB; k += blockDim.x) {
            float s = 0.f;
            for (int d = 0; d < EDIM; d++) { float e = embed[d * NEMB + k]; s += e * e; }
            g_enorm[k] = s;
        }
        return;
    }
    const int CIN  = c_layers[L][2], COUT = c_layers[L][3];
    const int KPAD = c_layers[L][4], CW   = c_layers[L][5];
    const int woff = c_layers[L][6], boff = c_layers[L][7];
    const float* W = P.in[c_layers[L][0]];
    const float* b = P.in[c_layers[L][1]];
    for (int e = threadIdx.x; e < KPAD * CW; e += blockDim.x) {
        int k = e / CW, c = e - (e / CW) * CW;
        float v = (k < CIN && c < COUT) ? W[c * CIN + k] : 0.f;
        g_Wt[woff + e] = v;
    }
    for (int c = threadIdx.x; c < CW; c += blockDim.x)
        g_bias[boff + c] = (c < COUT) ? b[c] : 0.f;
}

// ---------------- channel ownership (bank-conflict-free quads) ----------------
template<int MT>
__device__ __forceinline__ int chan(int ty, int m) {
    if constexpr (MT == 8) return (m < 4) ? ty * 4 + m : 128 + ty * 4 + (m - 4);
    else if constexpr (MT == 6) return (m < 4) ? ty * 4 + m : 128 + ty * 2 + (m - 4);
    else if constexpr (MT == 4) return ty * 4 + m;
    else if constexpr (MT == 2) return ty * 2 + m;
    else return ty;
}

template<int MT>
__device__ __forceinline__ void load_wf(const float* Wrow, int ty, float* wf) {
    if constexpr (MT == 8) {
        float4 a = *reinterpret_cast<const float4*>(Wrow + ty * 4);
        float4 b = *reinterpret_cast<const float4*>(Wrow + 128 + ty * 4);
        wf[0] = a.x; wf[1] = a.y; wf[2] = a.z; wf[3] = a.w;
        wf[4] = b.x; wf[5] = b.y; wf[6] = b.z; wf[7] = b.w;
    } else if constexpr (MT == 6) {
        float4 a = *reinterpret_cast<const float4*>(Wrow + ty * 4);
        float2 b = *reinterpret_cast<const float2*>(Wrow + 128 + ty * 2);
        wf[0] = a.x; wf[1] = a.y; wf[2] = a.z; wf[3] = a.w;
        wf[4] = b.x; wf[5] = b.y;
    } else if constexpr (MT == 4) {
        float4 a = *reinterpret_cast<const float4*>(Wrow + ty * 4);
        wf[0] = a.x; wf[1] = a.y; wf[2] = a.z; wf[3] = a.w;
    } else if constexpr (MT == 2) {
        float2 a = *reinterpret_cast<const float2*>(Wrow + ty * 2);
        wf[0] = a.x; wf[1] = a.y;
    } else {
        wf[0] = Wrow[ty];
    }
}

// ---------------- fused 1x1-conv layer (in-place, 1 barrier per chunk) ----------------
// OUT[c][t] = (RES? OUT[c][t]:0) + bias[c] + sum_k W[c][k]*(PRE? relu(IN[k][t]) : IN[k][t])
// 128 threads: 32 channel-groups (MT ch) x 4 token-groups (8 tokens)
// Barrier scheme: one __syncthreads per chunk proves (a) everyone's cp.asyncs of
// chunk kb landed (each thread did wait_group 0 first) and (b) everyone finished
// computing chunk kb-1, so buf (kb+1)&1 (which held kb-1) is safe to overwrite.
template<int CW, int KPAD, int KBT, bool PRE, bool POST, bool RES, bool STAGE>
__device__ __noinline__ void conv_layer(const float* __restrict__ Wt,
                                        const float* __restrict__ bias,
                                        const float* __restrict__ IN,
                                        float* __restrict__ OUT,
                                        float* __restrict__ Ws, int tid)
{
    constexpr int MT = CW / 32;
    constexpr int NK = KPAD / KBT;
    constexpr int CHUNKF = KBT * CW;
    static_assert(CHUNKF <= WBUFF, "chunk too big");

    const int tx = tid & 3;
    const int ty = tid >> 2;      // 0..31
    const int j0 = tx * 8;

    float bv[MT];
#pragma unroll
    for (int m = 0; m < MT; m++) bv[m] = __ldg(bias + chan<MT>(ty, m));

    ULL acc[4][MT];
#pragma unroll
    for (int t = 0; t < 4; t++)
#pragma unroll
        for (int m = 0; m < MT; m++) acc[t][m] = 0ull;

    __syncthreads();   // entry: prev-layer writes visible; Ws free

    // stage chunk 0
    {
        const float4* src = reinterpret_cast<const float4*>(Wt);
        float4* dst = reinterpret_cast<float4*>(Ws);
#pragma unroll
        for (int i = tid; i < CHUNKF / 4; i += THREADS)
            cp_async16(smem_u32(dst + i), src + i);
        asm volatile("cp.async.commit_group;\n" ::: "memory");
    }

    for (int kb = 0; kb < NK; kb++) {
        asm volatile("cp.async.wait_group 0;\n" ::: "memory");
        __syncthreads();   // the single per-chunk barrier
        if (kb + 1 < NK) {
            const float4* src = reinterpret_cast<const float4*>(Wt + (kb + 1) * CHUNKF);
            float4* dst = reinterpret_cast<float4*>(Ws + ((kb + 1) & 1) * WBUFF);
#pragma unroll
            for (int i = tid; i < CHUNKF / 4; i += THREADS)
                cp_async16(smem_u32(dst + i), src + i);
            asm volatile("cp.async.commit_group;\n" ::: "memory");
        }

        const float* Wk  = Ws + (kb & 1) * WBUFF;
        const float* inb = IN + kb * KBT * LDA + j0;

#pragma unroll 8
        for (int kk = 0; kk < KBT; kk++) {
            float4 va = *reinterpret_cast<const float4*>(inb + kk * LDA);
            float4 vb = *reinterpret_cast<const float4*>(inb + kk * LDA + 4);
            if (PRE) {
                va.x = fmaxf(va.x, 0.f); va.y = fmaxf(va.y, 0.f);
                va.z = fmaxf(va.z, 0.f); va.w = fmaxf(va.w, 0.f);
                vb.x = fmaxf(vb.x, 0.f); vb.y = fmaxf(vb.y, 0.f);
                vb.z = fmaxf(vb.z, 0.f); vb.w = fmaxf(vb.w, 0.f);
            }
            ULL t0 = pack2(va.x, va.y), t1 = pack2(va.z, va.w);
            ULL t2 = pack2(vb.x, vb.y), t3 = pack2(vb.z, vb.w);
            float wf[MT];
            load_wf<MT>(Wk + kk * CW, ty, wf);
#pragma unroll
            for (int m = 0; m < MT; m++) {
                ULL wd = pack2(wf[m], wf[m]);
                fma2(acc[0][m], wd, t0);
                fma2(acc[1][m], wd, t1);
                fma2(acc[2][m], wd, t2);
                fma2(acc[3][m], wd, t3);
            }
        }
    }

    // in-place staging barrier: all threads finished reading IN
    if (STAGE) __syncthreads();

    // epilogue: thread exclusively owns (ch, 8-token) slots of OUT
#pragma unroll
    for (int m = 0; m < MT; m++) {
        float r[8];
        unpack2(acc[0][m], r[0], r[1]);
        unpack2(acc[1][m], r[2], r[3]);
        unpack2(acc[2][m], r[4], r[5]);
        unpack2(acc[3][m], r[6], r[7]);
        float* op = OUT + chan<MT>(ty, m) * LDA + j0;
        float4 o0, o1;
        o0.x = r[0] + bv[m]; o0.y = r[1] + bv[m];
        o0.z = r[2] + bv[m]; o0.w = r[3] + bv[m];
        o1.x = r[4] + bv[m]; o1.y = r[5] + bv[m];
        o1.z = r[6] + bv[m]; o1.w = r[7] + bv[m];
        if (RES) {
            float4 e0 = *reinterpret_cast<float4*>(op);
            float4 e1 = *reinterpret_cast<float4*>(op + 4);
            o0.x += e0.x; o0.y += e0.y; o0.z += e0.z; o0.w += e0.w;
            o1.x += e1.x; o1.y += e1.y; o1.z += e1.z; o1.w += e1.w;
        }
        if (POST) {
            o0.x = fmaxf(o0.x, 0.f); o0.y = fmaxf(o0.y, 0.f);
            o0.z = fmaxf(o0.z, 0.f); o0.w = fmaxf(o0.w, 0.f);
            o1.x = fmaxf(o1.x, 0.f); o1.y = fmaxf(o1.y, 0.f);
            o1.z = fmaxf(o1.z, 0.f); o1.w = fmaxf(o1.w, 0.f);
        }
        *reinterpret_cast<float4*>(op)     = o0;
        *reinterpret_cast<float4*>(op + 4) = o1;
    }
}

#define LCONV(L, CW, KPAD, KBT, PRE, POST, RES, STAGE, INB, OUTB) \
    conv_layer<CW, KPAD, KBT, PRE, POST, RES, STAGE>(g_Wt + c_layers[L][6], g_bias + c_layers[L][7], INB, OUTB, Ws, tid)

// ---------------- main fused kernel ----------------
__global__ void __launch_bounds__(THREADS, 3) vqvae_kernel(Params P)
{
    extern __shared__ float sm[];
    float* A    = sm + SM_A;             // 288 rows x LDA
    float* T32  = A + 256 * LDA;         // resblock intermediate rows 256..287
    float* Ws   = sm + SM_W;             // weight ring (VQ reuses as Es)
    float* wsum = sm + SM_AUX;           // [8]

    const int tid = threadIdx.x;
    const int n0  = blockIdx.x * TILE;

    // ---- load x tile: [tok][c] -> [c][tok]; zero-pad rows 165..175 ----
    const float* x = P.in[0];
    for (int idx = tid; idx < 176 * TILE; idx += THREADS) {
        int c = idx % 176;
        int j = idx / 176;
        A[c * LDA + j] = (c < CINN) ? x[(n0 + j) * CINN + c] : 0.f;
    }

    // ---- encoder (all in-place in A; resblock mids in T32) ----
    LCONV(0, 128, 176, 16, false, true,  false, true,  A,   A  );
    LCONV(1, 256, 128, 16, false, true,  false, true,  A,   A  );
    LCONV(2, 256, 256, 16, false, false, false, true,  A,   A  );
    LCONV(3,  32, 256, 128, true, true,  false, false, A,   T32);
    LCONV(4, 256,  32, 16, false, false, true,  false, T32, A  );
    LCONV(5,  32, 256, 128, true, true,  false, false, A,   T32);
    LCONV(6, 256,  32, 16, false, false, true,  false, T32, A  );
    LCONV(7,  64, 256, 64, true,  false, false, true,  A,   A  );   // z -> rows 0..63

    // ---- vector quantize (z in A rows 0..63; norms precomputed) ----
    {
        const float* embed = P.in[17];
        float* Es = Ws;                 // [64 d][64 codes] = 16KB
        const int j = tid >> 2;         // token 0..31
        const int q = tid & 3;          // code 16-chunk within 64-code block
        float best = 3.4e38f; int bidx = 0;

        for (int cb = 0; cb < 8; cb++) {
            __syncthreads();            // Es free (everyone past previous use)
#pragma unroll
            for (int i = 0; i < 32; i++) {
                int idx = i * THREADS + tid;
                int kk = idx & 63, d = idx >> 6;
                Es[d * 64 + kk] = __ldg(embed + d * NEMB + cb * 64 + kk);
            }
            __syncthreads();

            ULL dot[8];
#pragma unroll
            for (int g = 0; g < 8; g++) dot[g] = 0ull;
#pragma unroll 8
            for (int d = 0; d < EDIM; d++) {
                float z = A[d * LDA + j];
                ULL z2 = pack2(z, z);
                const ulonglong2* er = reinterpret_cast<const ulonglong2*>(Es + d * 64 + q * 16);
                ulonglong2 e0 = er[0], e1 = er[1], e2 = er[2], e3 = er[3];
                fma2(dot[0], z2, e0.x); fma2(dot[1], z2, e0.y);
                fma2(dot[2], z2, e1.x); fma2(dot[3], z2, e1.y);
                fma2(dot[4], z2, e2.x); fma2(dot[5], z2, e2.y);
                fma2(dot[6], z2, e3.x); fma2(dot[7], z2, e3.y);
            }
#pragma unroll
            for (int g = 0; g < 8; g++) {
                float d0, d1; unpack2(dot[g], d0, d1);
                int kbv = cb * 64 + q * 16 + 2 * g;
                float s0 = __ldg(g_enorm + kbv)     - 2.f * d0;
                float s1 = __ldg(g_enorm + kbv + 1) - 2.f * d1;
                if (s0 < best) { best = s0; bidx = kbv; }
                if (s1 < best) { best = s1; bidx = kbv + 1; }
            }
        }
        // argmin across 4 lanes of this token (tie -> lower index)
#pragma unroll
        for (int off = 1; off < 4; off <<= 1) {
            float ob = __shfl_xor_sync(0xffffffffu, best, off);
            int   oi = __shfl_xor_sync(0xffffffffu, bidx, off);
            if (ob < best || (ob == best && oi < bidx)) { best = ob; bidx = oi; }
        }
        // gather codebook vector into A (in place), accumulate diff partial
        float dsum = 0.f;
#pragma unroll
        for (int dd = 0; dd < 16; dd++) {
            int d = q * 16 + dd;
            float e = __ldg(embed + d * NEMB + bidx);
            float z = A[d * LDA + j];
            A[d * LDA + j] = e;
            float df = e - z;
            dsum += df * df;
        }
#pragma unroll
        for (int off = 16; off > 0; off >>= 1)
            dsum += __shfl_xor_sync(0xffffffffu, dsum, off);
        if ((tid & 31) == 0) wsum[tid >> 5] = dsum;
        __syncthreads();
        if (tid == 0)
            g_part[blockIdx.x] = wsum[0] + wsum[1] + wsum[2] + wsum[3];
    }

    // ---- decoder ----
    LCONV( 8, 256,  64, 16, false, false, false, true,  A,   A  );
    LCONV( 9,  32, 256, 128, true, true,  false, false, A,   T32);
    LCONV(10, 256,  32, 16, false, false, true,  false, T32, A  );
    LCONV(11,  32, 256, 128, true, true,  false, false, A,   T32);
    LCONV(12, 256,  32, 16, false, false, true,  false, T32, A  );
    LCONV(13, 128, 256, 32, true,  true,  false, true,  A,   A  );
    LCONV(14, 192, 128, 16, false, false, false, true,  A,   A  );
    __syncthreads();

    // ---- store output tile: [c][tok] -> [tok][c] ----
    for (int idx = tid; idx < CINN * TILE; idx += THREADS) {
        int j = idx / CINN;
        int c = idx - j * CINN;
        P.out[(n0 + j) * CINN + c] = A[c * LDA + j];
    }

    // ---- last-block finalize of diff ----
    __threadfence();
    __shared__ unsigned int is_last;
    if (tid == 0) is_last = (atomicAdd(&g_count, 1u) == NBLK - 1) ? 1u : 0u;
    __syncthreads();
    if (is_last) {
        float s = 0.f;
        for (int i = tid; i < NBLK; i += THREADS) s += g_part[i];
#pragma unroll
        for (int off = 16; off > 0; off >>= 1)
            s += __shfl_xor_sync(0xffffffffu, s, off);
        if ((tid & 31) == 0) wsum[tid >> 5] = s;
        __syncthreads();
        if (tid == 0) {
            float t = wsum[0] + wsum[1] + wsum[2] + wsum[3];
            if (P.out_size > DEC_ELEMS)
                P.out[DEC_ELEMS] = t * (1.0f / 8388608.0f);  // mean over N*EDIM
            g_count = 0u;   // reset for next graph replay
        }
    }
}

// ---------------- launch ----------------
extern "C" void kernel_launch(void* const* d_in, const int* in_sizes, int n_in,
                              void* d_out, int out_size)
{
    (void)in_sizes; (void)n_in;
    Params P;
    for (int i = 0; i < 32; i++) P.in[i] = (const float*)d_in[i];
    P.out = (float*)d_out;
    P.out_size = out_size;

    static bool attr_set = false;
    if (!attr_set) {
        cudaFuncSetAttribute(vqvae_kernel, cudaFuncAttributeMaxDynamicSharedMemorySize, SMEM_BYTES);
        attr_set = true;
    }
    prep_kernel<<<16, 256>>>(P);
    vqvae_kernel<<<NBLK, THREADS, SMEM_BYTES>>>(P);
}

// round 13
// speedup vs baseline: 1.6887x; 1.2344x over previous
#include <cuda_runtime.h>
#include <cstdint>

// ---------------- problem constants ----------------
#define BN   32
#define TN   4096
#define CINN 165
#define EDIM 64
#define NEMB 512
#define NTOK (BN*TN)          // 131072
#define TILE 32               // tokens per CTA
#define NBLK (NTOK/TILE)      // 4096
#define LDA  32               // token-row stride (floats) = 128B aligned
#define DEC_ELEMS (NTOK*CINN) // 21626880
#define THREADS 128

// shared layout (floats)
#define AROWS  288
#define SM_A   0
#define SM_W   (AROWS*LDA)          // 9216
#define WBUFF  4096
#define SM_AUX (SM_W + 2*WBUFF)     // 17408
#define SM_FLOATS (SM_AUX + 304)
#define SMEM_BYTES (SM_FLOATS*4)    // ~70.8 KB -> 3 CTAs/SM

typedef unsigned long long ULL;

__device__ float g_Wt[276480];
__device__ float g_bias[2432];
__device__ float g_enorm[NEMB];
__device__ float g_part[NBLK];
__device__ unsigned int g_count;
__device__ float g_X[176 * NTOK];   // pre-transposed input  [c][tok]
__device__ float g_O[165 * NTOK];   // pre-transposed output [c][tok]

// layer metadata: {w_in_idx, b_in_idx, CIN, COUT, KPAD, CW, woff, boff}
__constant__ int c_layers[15][8] = {
    { 1,  2, 165, 128, 176, 128,      0,    0},
    { 3,  4, 128, 256, 128, 256,  22528,  128},
    { 5,  6, 256, 256, 256, 256,  55296,  384},
    { 7,  8, 256,  32, 256,  32, 120832,  640},
    { 9, 10,  32, 256,  32, 256, 129024,  672},
    {11, 12, 256,  32, 256,  32, 137216,  928},
    {13, 14,  32, 256,  32, 256, 145408,  960},
    {15, 16, 256,  64, 256,  64, 153600, 1216},
    {18, 19,  64, 256,  64, 256, 169984, 1280},
    {20, 21, 256,  32, 256,  32, 186368, 1536},
    {22, 23,  32, 256,  32, 256, 194560, 1568},
    {24, 25, 256,  32, 256,  32, 202752, 1824},
    {26, 27,  32, 256,  32, 256, 210944, 1856},
    {28, 29, 256, 128, 256, 128, 219136, 2112},
    {30, 31, 128, 165, 128, 192, 251904, 2240},
};

// ---------------- f32x2 helpers ----------------
__device__ __forceinline__ ULL pack2(float x, float y) {
    ULL r; asm("mov.b64 %0, {%1, %2};" : "=l"(r) : "f"(x), "f"(y)); return r;
}
__device__ __forceinline__ void unpack2(ULL v, float& x, float& y) {
    asm("mov.b64 {%0, %1}, %2;" : "=f"(x), "=f"(y) : "l"(v));
}
__device__ __forceinline__ void fma2(ULL& d, ULL a, ULL b) {
    asm("fma.rn.f32x2 %0, %1, %2, %0;" : "+l"(d) : "l"(a), "l"(b));
}
__device__ __forceinline__ uint32_t smem_u32(const void* p) {
    uint32_t a;
    asm("{ .reg .u64 t; cvta.to.shared.u64 t, %1; cvt.u32.u64 %0, t; }" : "=r"(a) : "l"(p));
    return a;
}
__device__ __forceinline__ void cp_async16(uint32_t dst, const void* src) {
    asm volatile("cp.async.cg.shared.global [%0], [%1], 16;\n" :: "r"(dst), "l"(src));
}

struct Params { const float* in[32]; float* out; int out_size; };

// ---------------- prep: weights transpose+pad, codebook norms ----------------
__global__ void prep_kernel(Params P) {
    const int L = blockIdx.x;
    if (L == 15) {
        const float* embed = P.in[17];
        for (int k = threadIdx.x; k < NEMB; k += blockDim.x) {
            float s = 0.f;
            for (int d = 0; d < EDIM; d++) { float e = embed[d * NEMB + k]; s += e * e; }
            g_enorm[k] = s;
        }
        return;
    }
    const int CIN  = c_layers[L][2], COUT = c_layers[L][3];
    const int KPAD = c_layers[L][4], CW   = c_layers[L][5];
    const int woff = c_layers[L][6], boff = c_layers[L][7];
    const float* W = P.in[c_layers[L][0]];
    const float* b = P.in[c_layers[L][1]];
    for (int e = threadIdx.x; e < KPAD * CW; e += blockDim.x) {
        int k = e / CW, c = e - (e / CW) * CW;
        float v = (k < CIN && c < COUT) ? W[c * CIN + k] : 0.f;
        g_Wt[woff + e] = v;
    }
    for (int c = threadIdx.x; c < CW; c += blockDim.x)
        g_bias[boff + c] = (c < COUT) ? b[c] : 0.f;
}

// ---------------- prep_x: x[tok][165] -> g_X[176][NTOK] (tiled transpose) ----------------
__global__ void prep_x(Params P) {
    __shared__ float t[32][33];
    const float* x = P.in[0];
    int bx = blockIdx.x, by = blockIdx.y;
    int tx = threadIdx.x, ty = threadIdx.y;
#pragma unroll
    for (int i = 0; i < 4; i++) {
        int r = ty + i * 8;
        int c = by * 32 + r;
        int tok = bx * 32 + tx;
        t[r][tx] = (c < CINN) ? x[tok * CINN + c] : 0.f;
    }
    __syncthreads();
#pragma unroll
    for (int i = 0; i < 4; i++) {
        int r = ty + i * 8;
        int c = by * 32 + tx;
        int tok = bx * 32 + r;
        if (c < 176) g_X[c * NTOK + tok] = t[tx][r];
    }
}

// ---------------- post_out: g_O[165][NTOK] -> out[tok][165] ----------------
__global__ void post_out(Params P) {
    __shared__ float t[32][33];
    int bx = blockIdx.x, by = blockIdx.y;
    int tx = threadIdx.x, ty = threadIdx.y;
#pragma unroll
    for (int i = 0; i < 4; i++) {
        int r = ty + i * 8;
        int c = by * 32 + r;
        int tok = bx * 32 + tx;
        if (c < CINN) t[r][tx] = g_O[c * NTOK + tok];
    }
    __syncthreads();
#pragma unroll
    for (int i = 0; i < 4; i++) {
        int r = ty + i * 8;
        int c = by * 32 + tx;
        int tok = bx * 32 + r;
        if (c < CINN) P.out[tok * CINN + c] = t[tx][r];
    }
}

// ---------------- channel ownership (bank-conflict-free quads) ----------------
template<int MT>
__device__ __forceinline__ int chan(int ty, int m) {
    if constexpr (MT == 8) return (m < 4) ? ty * 4 + m : 128 + ty * 4 + (m - 4);
    else if constexpr (MT == 6) return (m < 4) ? ty * 4 + m : 128 + ty * 2 + (m - 4);
    else if constexpr (MT == 4) return ty * 4 + m;
    else if constexpr (MT == 2) return ty * 2 + m;
    else return ty;
}

template<int MT>
__device__ __forceinline__ void load_wf(const float* Wrow, int ty, float* wf) {
    if constexpr (MT == 8) {
        float4 a = *reinterpret_cast<const float4*>(Wrow + ty * 4);
        float4 b = *reinterpret_cast<const float4*>(Wrow + 128 + ty * 4);
        wf[0] = a.x; wf[1] = a.y; wf[2] = a.z; wf[3] = a.w;
        wf[4] = b.x; wf[5] = b.y; wf[6] = b.z; wf[7] = b.w;
    } else if constexpr (MT == 6) {
        float4 a = *reinterpret_cast<const float4*>(Wrow + ty * 4);
        float2 b = *reinterpret_cast<const float2*>(Wrow + 128 + ty * 2);
        wf[0] = a.x; wf[1] = a.y; wf[2] = a.z; wf[3] = a.w;
        wf[4] = b.x; wf[5] = b.y;
    } else if constexpr (MT == 4) {
        float4 a = *reinterpret_cast<const float4*>(Wrow + ty * 4);
        wf[0] = a.x; wf[1] = a.y; wf[2] = a.z; wf[3] = a.w;
    } else if constexpr (MT == 2) {
        float2 a = *reinterpret_cast<const float2*>(Wrow + ty * 2);
        wf[0] = a.x; wf[1] = a.y;
    } else {
        wf[0] = Wrow[ty];
    }
}

// ---------------- fused 1x1-conv layer ----------------
template<int CW, int KPAD, int KBT, bool PRE, bool POST, bool RES, bool STAGE>
__device__ __noinline__ void conv_layer(const float* __restrict__ Wt,
                                        const float* __restrict__ bias,
                                        const float* __restrict__ IN,
                                        float* __restrict__ OUT,
                                        float* __restrict__ Ws, int tid)
{
    constexpr int MT = CW / 32;
    constexpr int NK = KPAD / KBT;
    constexpr int CHUNKF = KBT * CW;
    static_assert(CHUNKF <= WBUFF, "chunk too big");

    const int tx = tid & 3;
    const int ty = tid >> 2;
    const int j0 = tx * 8;

    float bv[MT];
#pragma unroll
    for (int m = 0; m < MT; m++) bv[m] = __ldg(bias + chan<MT>(ty, m));

    ULL acc[4][MT];
#pragma unroll
    for (int t = 0; t < 4; t++)
#pragma unroll
        for (int m = 0; m < MT; m++) acc[t][m] = 0ull;

    __syncthreads();   // prev-layer writes visible; Ws free

    {
        const float4* src = reinterpret_cast<const float4*>(Wt);
        float4* dst = reinterpret_cast<float4*>(Ws);
#pragma unroll
        for (int i = tid; i < CHUNKF / 4; i += THREADS)
            cp_async16(smem_u32(dst + i), src + i);
        asm volatile("cp.async.commit_group;\n" ::: "memory");
    }

    for (int kb = 0; kb < NK; kb++) {
        asm volatile("cp.async.wait_group 0;\n" ::: "memory");
        __syncthreads();
        if (kb + 1 < NK) {
            const float4* src = reinterpret_cast<const float4*>(Wt + (kb + 1) * CHUNKF);
            float4* dst = reinterpret_cast<float4*>(Ws + ((kb + 1) & 1) * WBUFF);
#pragma unroll
            for (int i = tid; i < CHUNKF / 4; i += THREADS)
                cp_async16(smem_u32(dst + i), src + i);
            asm volatile("cp.async.commit_group;\n" ::: "memory");
        }

        const float* Wk  = Ws + (kb & 1) * WBUFF;
        const float* inb = IN + kb * KBT * LDA + j0;

#pragma unroll 8
        for (int kk = 0; kk < KBT; kk++) {
            float4 va = *reinterpret_cast<const float4*>(inb + kk * LDA);
            float4 vb = *reinterpret_cast<const float4*>(inb + kk * LDA + 4);
            if (PRE) {
                va.x = fmaxf(va.x, 0.f); va.y = fmaxf(va.y, 0.f);
                va.z = fmaxf(va.z, 0.f); va.w = fmaxf(va.w, 0.f);
                vb.x = fmaxf(vb.x, 0.f); vb.y = fmaxf(vb.y, 0.f);
                vb.z = fmaxf(vb.z, 0.f); vb.w = fmaxf(vb.w, 0.f);
            }
            ULL t0 = pack2(va.x, va.y), t1 = pack2(va.z, va.w);
            ULL t2 = pack2(vb.x, vb.y), t3 = pack2(vb.z, vb.w);
            float wf[MT];
            load_wf<MT>(Wk + kk * CW, ty, wf);
#pragma unroll
            for (int m = 0; m < MT; m++) {
                ULL wd = pack2(wf[m], wf[m]);
                fma2(acc[0][m], wd, t0);
                fma2(acc[1][m], wd, t1);
                fma2(acc[2][m], wd, t2);
                fma2(acc[3][m], wd, t3);
            }
        }
    }

    if (STAGE) __syncthreads();

#pragma unroll
    for (int m = 0; m < MT; m++) {
        float r[8];
        unpack2(acc[0][m], r[0], r[1]);
        unpack2(acc[1][m], r[2], r[3]);
        unpack2(acc[2][m], r[4], r[5]);
        unpack2(acc[3][m], r[6], r[7]);
        float* op = OUT + chan<MT>(ty, m) * LDA + j0;
        float4 o0, o1;
        o0.x = r[0] + bv[m]; o0.y = r[1] + bv[m];
        o0.z = r[2] + bv[m]; o0.w = r[3] + bv[m];
        o1.x = r[4] + bv[m]; o1.y = r[5] + bv[m];
        o1.z = r[6] + bv[m]; o1.w = r[7] + bv[m];
        if (RES) {
            float4 e0 = *reinterpret_cast<float4*>(op);
            float4 e1 = *reinterpret_cast<float4*>(op + 4);
            o0.x += e0.x; o0.y += e0.y; o0.z += e0.z; o0.w += e0.w;
            o1.x += e1.x; o1.y += e1.y; o1.z += e1.z; o1.w += e1.w;
        }
        if (POST) {
            o0.x = fmaxf(o0.x, 0.f); o0.y = fmaxf(o0.y, 0.f);
            o0.z = fmaxf(o0.z, 0.f); o0.w = fmaxf(o0.w, 0.f);
            o1.x = fmaxf(o1.x, 0.f); o1.y = fmaxf(o1.y, 0.f);
            o1.z = fmaxf(o1.z, 0.f); o1.w = fmaxf(o1.w, 0.f);
        }
        *reinterpret_cast<float4*>(op)     = o0;
        *reinterpret_cast<float4*>(op + 4) = o1;
    }
}

#define LCONV(L, CW, KPAD, KBT, PRE, POST, RES, STAGE, INB, OUTB) \
    conv_layer<CW, KPAD, KBT, PRE, POST, RES, STAGE>(g_Wt + c_layers[L][6], g_bias + c_layers[L][7], INB, OUTB, Ws, tid)

// ---------------- main fused kernel ----------------
__global__ void __launch_bounds__(THREADS, 3) vqvae_kernel(Params P)
{
    extern __shared__ float sm[];
    float* A    = sm + SM_A;             // 288 rows x LDA
    float* T32  = A + 256 * LDA;
    float* Ws   = sm + SM_W;
    float* cand_d = sm + SM_AUX;         // [128]
    float* cand_i = cand_d + 128;        // [128] (as float-bits ints)
    float* ibest  = cand_i + 128;        // [32]
    float* wsum   = ibest + 32;          // [8]

    const int tid = threadIdx.x;
    const int n0  = blockIdx.x * TILE;

    // ---- load pre-transposed x tile: coalesced gmem, conflict-free smem ----
    for (int idx = tid; idx < 176 * TILE; idx += THREADS) {
        int c = idx >> 5;
        int j = idx & 31;
        A[c * LDA + j] = g_X[c * NTOK + n0 + j];
    }

    // ---- encoder ----
    LCONV(0, 128, 176, 16, false, true,  false, true,  A,   A  );
    LCONV(1, 256, 128, 16, false, true,  false, true,  A,   A  );
    LCONV(2, 256, 256, 16, false, false, false, true,  A,   A  );
    LCONV(3,  32, 256, 128, true, true,  false, false, A,   T32);
    LCONV(4, 256,  32, 16, false, false, true,  false, T32, A  );
    LCONV(5,  32, 256, 128, true, true,  false, false, A,   T32);
    LCONV(6, 256,  32, 16, false, false, true,  false, T32, A  );
    LCONV(7,  64, 256, 64, true,  false, false, true,  A,   A  );   // z -> rows 0..63

    // ---- vector quantize: warp w handles codebook blocks {2w, 2w+1};
    //      lane = (cgrp = l>>2 : 8 codes, jgrp = l&3 : 8 tokens) ----
    {
        const float* embed = P.in[17];
        const int l = tid & 31;
        const int w = tid >> 5;
        const int cgrp = l >> 2;
        const int jgrp = l & 3;
        const int j0v = jgrp * 8;

        __syncthreads();   // z stable

        float best[8]; int bidx[8];
#pragma unroll
        for (int t = 0; t < 8; t++) { best[t] = 3.4e38f; bidx[t] = 0; }

#pragma unroll
        for (int cbi = 0; cbi < 2; cbi++) {
            const int cb = w * 2 + cbi;
            const int cbase = cb * 64 + cgrp * 8;

            ULL acc[4][8];
#pragma unroll
            for (int c2 = 0; c2 < 4; c2++)
#pragma unroll
                for (int t = 0; t < 8; t++) acc[c2][t] = 0ull;

#pragma unroll 8
            for (int d = 0; d < EDIM; d++) {
                const float* zr = A + d * LDA + j0v;
                float4 za = *reinterpret_cast<const float4*>(zr);
                float4 zb = *reinterpret_cast<const float4*>(zr + 4);
                ULL zd[8];
                zd[0] = pack2(za.x, za.x); zd[1] = pack2(za.y, za.y);
                zd[2] = pack2(za.z, za.z); zd[3] = pack2(za.w, za.w);
                zd[4] = pack2(zb.x, zb.x); zd[5] = pack2(zb.y, zb.y);
                zd[6] = pack2(zb.z, zb.z); zd[7] = pack2(zb.w, zb.w);
                const ulonglong2* ep =
                    reinterpret_cast<const ulonglong2*>(embed + d * NEMB + cbase);
                ulonglong2 e01 = __ldg(ep), e23 = __ldg(ep + 1);
                ULL ec[4] = {e01.x, e01.y, e23.x, e23.y};
#pragma unroll
                for (int c2 = 0; c2 < 4; c2++)
#pragma unroll
                    for (int t = 0; t < 8; t++)
                        fma2(acc[c2][t], ec[c2], zd[t]);
            }

            float4 en0 = __ldg(reinterpret_cast<const float4*>(g_enorm + cbase));
            float4 en1 = __ldg(reinterpret_cast<const float4*>(g_enorm + cbase + 4));
            float en[8] = {en0.x, en0.y, en0.z, en0.w, en1.x, en1.y, en1.z, en1.w};
#pragma unroll
            for (int c2 = 0; c2 < 4; c2++) {
                int c = cbase + c2 * 2;
#pragma unroll
                for (int t = 0; t < 8; t++) {
                    float d0, d1; unpack2(acc[c2][t], d0, d1);
                    float s0 = en[c2 * 2]     - 2.f * d0;
                    float s1 = en[c2 * 2 + 1] - 2.f * d1;
                    if (s0 < best[t]) { best[t] = s0; bidx[t] = c; }
                    if (s1 < best[t]) { best[t] = s1; bidx[t] = c + 1; }
                }
            }
        }

        // reduce over the 8 cgrp-lanes sharing this jgrp (tie -> lower idx)
#pragma unroll
        for (int off = 4; off < 32; off <<= 1) {
#pragma unroll
            for (int t = 0; t < 8; t++) {
                float ob = __shfl_xor_sync(0xffffffffu, best[t], off);
                int   oi = __shfl_xor_sync(0xffffffffu, bidx[t], off);
                if (ob < best[t] || (ob == best[t] && oi < bidx[t])) {
                    best[t] = ob; bidx[t] = oi;
                }
            }
        }
        if (cgrp == 0) {
#pragma unroll
            for (int t = 0; t < 8; t++) {
                cand_d[w * 32 + j0v + t] = best[t];
                reinterpret_cast<int*>(cand_i)[w * 32 + j0v + t] = bidx[t];
            }
        }
        __syncthreads();
        if (tid < 32) {
            float bb = cand_d[tid];
            int   bi = reinterpret_cast<int*>(cand_i)[tid];
#pragma unroll
            for (int ww = 1; ww < 4; ww++) {
                float ob = cand_d[ww * 32 + tid];
                int   oi = reinterpret_cast<int*>(cand_i)[ww * 32 + tid];
                if (ob < bb || (ob == bb && oi < bi)) { bb = ob; bi = oi; }
            }
            reinterpret_cast<int*>(ibest)[tid] = bi;
        }
        __syncthreads();

        // gather codebook vector into A (in place), accumulate diff partial
        const int j = tid >> 2;
        const int q = tid & 3;
        const int bsel = reinterpret_cast<int*>(ibest)[j];
        float dsum = 0.f;
#pragma unroll
        for (int dd = 0; dd < 16; dd++) {
            int d = q * 16 + dd;
            float e = __ldg(embed + d * NEMB + bsel);
            float z = A[d * LDA + j];
            A[d * LDA + j] = e;
            float df = e - z;
            dsum += df * df;
        }
#pragma unroll
        for (int off = 16; off > 0; off >>= 1)
            dsum += __shfl_xor_sync(0xffffffffu, dsum, off);
        if ((tid & 31) == 0) wsum[tid >> 5] = dsum;
        __syncthreads();
        if (tid == 0)
            g_part[blockIdx.x] = wsum[0] + wsum[1] + wsum[2] + wsum[3];
    }

    // ---- decoder ----
    LCONV( 8, 256,  64, 16, false, false, false, true,  A,   A  );
    LCONV( 9,  32, 256, 128, true, true,  false, false, A,   T32);
    LCONV(10, 256,  32, 16, false, false, true,  false, T32, A  );
    LCONV(11,  32, 256, 128, true, true,  false, false, A,   T32);
    LCONV(12, 256,  32, 16, false, false, true,  false, T32, A  );
    LCONV(13, 128, 256, 32, true,  true,  false, true,  A,   A  );
    LCONV(14, 192, 128, 16, false, false, false, true,  A,   A  );
    __syncthreads();

    // ---- store output tile to transposed scratch: row reads, coalesced writes ----
    for (int idx = tid; idx < CINN * TILE; idx += THREADS) {
        int c = idx >> 5;
        int j = idx & 31;
        if (c < CINN) g_O[c * NTOK + n0 + j] = A[c * LDA + j];
    }

    // ---- last-block finalize of diff ----
    __threadfence();
    __shared__ unsigned int is_last;
    if (tid == 0) is_last = (atomicAdd(&g_count, 1u) == NBLK - 1) ? 1u : 0u;
    __syncthreads();
    if (is_last) {
        float s = 0.f;
        for (int i = tid; i < NBLK; i += THREADS) s += g_part[i];
#pragma unroll
        for (int off = 16; off > 0; off >>= 1)
            s += __shfl_xor_sync(0xffffffffu, s, off);
        if ((tid & 31) == 0) wsum[tid >> 5] = s;
        __syncthreads();
        if (tid == 0) {
            float t = wsum[0] + wsum[1] + wsum[2] + wsum[3];
            if (P.out_size > DEC_ELEMS)
                P.out[DEC_ELEMS] = t * (1.0f / 8388608.0f);
            g_count = 0u;
        }
    }
}

// ---------------- launch ----------------
extern "C" void kernel_launch(void* const* d_in, const int* in_sizes, int n_in,
                              void* d_out, int out_size)
{
    (void)in_sizes; (void)n_in;
    Params P;
    for (int i = 0; i < 32; i++) P.in[i] = (const float*)d_in[i];
    P.out = (float*)d_out;
    P.out_size = out_size;

    static bool attr_set = false;
    if (!attr_set) {
        cudaFuncSetAttribute(vqvae_kernel, cudaFuncAttributeMaxDynamicSharedMemorySize, SMEM_BYTES);
        attr_set = true;
    }
    prep_kernel<<<16, 256>>>(P);
    prep_x<<<dim3(NTOK / 32, 6), dim3(32, 8)>>>(P);
    vqvae_kernel<<<NBLK, THREADS, SMEM_BYTES>>>(P);
    post_out<<<dim3(NTOK / 32, 6), dim3(32, 8)>>>(P);
}

// round 14
// speedup vs baseline: 1.9383x; 1.1478x over previous
#include <cuda_runtime.h>
#include <cstdint>

// ---------------- problem constants ----------------
#define BN   32
#define TN   4096
#define CINN 165
#define EDIM 64
#define NEMB 512
#define NTOK (BN*TN)          // 131072
#define TILE 32               // tokens per CTA
#define NBLK (NTOK/TILE)      // 4096
#define LDA  32               // token-row stride (floats) = 128B aligned
#define DEC_ELEMS (NTOK*CINN) // 21626880
#define THREADS 128

// shared layout (floats)
#define AROWS  288
#define SM_A   0
#define SM_W   (AROWS*LDA)          // 9216
#define WBUFF  4096
#define SM_AUX (SM_W + 2*WBUFF)     // 17408
#define SM_FLOATS (SM_AUX + 304)
#define SMEM_BYTES (SM_FLOATS*4)    // ~70.8 KB -> 3 CTAs/SM

typedef unsigned long long ULL;

__device__ float g_Wt[276480];
__device__ float g_bias[2432];
__device__ float g_enorm[NEMB];
__device__ float g_part[NBLK];
__device__ unsigned int g_count;
__device__ float g_X[176 * NTOK];   // pre-transposed input  [c][tok]
__device__ float g_O[165 * NTOK];   // pre-transposed output [c][tok]

// layer metadata: {w_in_idx, b_in_idx, CIN, COUT, KPAD, CW, woff, boff}
__constant__ int c_layers[15][8] = {
    { 1,  2, 165, 128, 176, 128,      0,    0},
    { 3,  4, 128, 256, 128, 256,  22528,  128},
    { 5,  6, 256, 256, 256, 256,  55296,  384},
    { 7,  8, 256,  32, 256,  32, 120832,  640},
    { 9, 10,  32, 256,  32, 256, 129024,  672},
    {11, 12, 256,  32, 256,  32, 137216,  928},
    {13, 14,  32, 256,  32, 256, 145408,  960},
    {15, 16, 256,  64, 256,  64, 153600, 1216},
    {18, 19,  64, 256,  64, 256, 169984, 1280},
    {20, 21, 256,  32, 256,  32, 186368, 1536},
    {22, 23,  32, 256,  32, 256, 194560, 1568},
    {24, 25, 256,  32, 256,  32, 202752, 1824},
    {26, 27,  32, 256,  32, 256, 210944, 1856},
    {28, 29, 256, 128, 256, 128, 219136, 2112},
    {30, 31, 128, 165, 128, 192, 251904, 2240},
};

// ---------------- f32x2 helpers ----------------
__device__ __forceinline__ ULL pack2(float x, float y) {
    ULL r; asm("mov.b64 %0, {%1, %2};" : "=l"(r) : "f"(x), "f"(y)); return r;
}
__device__ __forceinline__ void unpack2(ULL v, float& x, float& y) {
    asm("mov.b64 {%0, %1}, %2;" : "=f"(x), "=f"(y) : "l"(v));
}
__device__ __forceinline__ void fma2(ULL& d, ULL a, ULL b) {
    asm("fma.rn.f32x2 %0, %1, %2, %0;" : "+l"(d) : "l"(a), "l"(b));
}
__device__ __forceinline__ uint32_t smem_u32(const void* p) {
    uint32_t a;
    asm("{ .reg .u64 t; cvta.to.shared.u64 t, %1; cvt.u32.u64 %0, t; }" : "=r"(a) : "l"(p));
    return a;
}
__device__ __forceinline__ void cp_async16(uint32_t dst, const void* src) {
    asm volatile("cp.async.cg.shared.global [%0], [%1], 16;\n" :: "r"(dst), "l"(src));
}

struct Params { const float* in[32]; float* out; int out_size; };

// ---------------- prep: weights transpose+pad, codebook norms ----------------
__global__ void prep_kernel(Params P) {
    const int L = blockIdx.x;
    if (L == 15) {
        const float* embed = P.in[17];
        for (int k = threadIdx.x; k < NEMB; k += blockDim.x) {
            float s = 0.f;
            for (int d = 0; d < EDIM; d++) { float e = embed[d * NEMB + k]; s += e * e; }
            g_enorm[k] = s;
        }
        return;
    }
    const int CIN  = c_layers[L][2], COUT = c_layers[L][3];
    const int KPAD = c_layers[L][4], CW   = c_layers[L][5];
    const int woff = c_layers[L][6], boff = c_layers[L][7];
    const float* W = P.in[c_layers[L][0]];
    const float* b = P.in[c_layers[L][1]];
    for (int e = threadIdx.x; e < KPAD * CW; e += blockDim.x) {
        int k = e / CW, c = e - (e / CW) * CW;
        float v = (k < CIN && c < COUT) ? W[c * CIN + k] : 0.f;
        g_Wt[woff + e] = v;
    }
    for (int c = threadIdx.x; c < CW; c += blockDim.x)
        g_bias[boff + c] = (c < COUT) ? b[c] : 0.f;
}

// ---------------- prep_x: x[tok][165] -> g_X[176][NTOK] (coalesced both sides) ----------------
__global__ void prep_x(Params P) {
    __shared__ float t[32][33];
    const float* x = P.in[0];
    int bx = blockIdx.x, by = blockIdx.y;
    int tx = threadIdx.x, ty = threadIdx.y;
#pragma unroll
    for (int i = 0; i < 4; i++) {
        int r = ty + i * 8;          // token row within tile
        int c = by * 32 + tx;        // channel (fast -> coalesced read)
        int tok = bx * 32 + r;
        t[r][tx] = (c < CINN) ? x[tok * CINN + c] : 0.f;
    }
    __syncthreads();
#pragma unroll
    for (int i = 0; i < 4; i++) {
        int c = by * 32 + ty + i * 8;    // channel row
        int tok = bx * 32 + tx;          // token (fast -> coalesced write)
        if (c < 176) g_X[c * NTOK + tok] = t[tx][ty + i * 8];
    }
}

// ---------------- post_out: g_O[165][NTOK] -> out[tok][165] ----------------
__global__ void post_out(Params P) {
    __shared__ float t[32][33];
    int bx = blockIdx.x, by = blockIdx.y;
    int tx = threadIdx.x, ty = threadIdx.y;
#pragma unroll
    for (int i = 0; i < 4; i++) {
        int r = ty + i * 8;
        int c = by * 32 + r;
        int tok = bx * 32 + tx;
        if (c < CINN) t[r][tx] = g_O[c * NTOK + tok];
    }
    __syncthreads();
#pragma unroll
    for (int i = 0; i < 4; i++) {
        int r = ty + i * 8;
        int c = by * 32 + tx;
        int tok = bx * 32 + r;
        if (c < CINN) P.out[tok * CINN + c] = t[tx][r];
    }
}

// ---------------- channel ownership (bank-conflict-free quads) ----------------
template<int MT>
__device__ __forceinline__ int chan(int ty, int m) {
    if constexpr (MT == 8) return (m < 4) ? ty * 4 + m : 128 + ty * 4 + (m - 4);
    else if constexpr (MT == 6) return (m < 4) ? ty * 4 + m : 128 + ty * 2 + (m - 4);
    else if constexpr (MT == 4) return ty * 4 + m;
    else return ty;
}

template<int MT>
__device__ __forceinline__ void load_wf(const float* Wrow, int ty, float* wf) {
    if constexpr (MT == 8) {
        float4 a = *reinterpret_cast<const float4*>(Wrow + ty * 4);
        float4 b = *reinterpret_cast<const float4*>(Wrow + 128 + ty * 4);
        wf[0] = a.x; wf[1] = a.y; wf[2] = a.z; wf[3] = a.w;
        wf[4] = b.x; wf[5] = b.y; wf[6] = b.z; wf[7] = b.w;
    } else if constexpr (MT == 6) {
        float4 a = *reinterpret_cast<const float4*>(Wrow + ty * 4);
        float2 b = *reinterpret_cast<const float2*>(Wrow + 128 + ty * 2);
        wf[0] = a.x; wf[1] = a.y; wf[2] = a.z; wf[3] = a.w;
        wf[4] = b.x; wf[5] = b.y;
    } else if constexpr (MT == 4) {
        float4 a = *reinterpret_cast<const float4*>(Wrow + ty * 4);
        wf[0] = a.x; wf[1] = a.y; wf[2] = a.z; wf[3] = a.w;
    }
}

// ---------------- fused 1x1-conv layer (wide channels: CW >= 128) ----------------
template<int CW, int KPAD, int KBT, bool PRE, bool POST, bool RES, bool STAGE>
__device__ __noinline__ void conv_layer(const float* __restrict__ Wt,
                                        const float* __restrict__ bias,
                                        const float* __restrict__ IN,
                                        float* __restrict__ OUT,
                                        float* __restrict__ Ws, int tid)
{
    constexpr int MT = CW / 32;
    constexpr int NK = KPAD / KBT;
    constexpr int CHUNKF = KBT * CW;
    static_assert(CHUNKF <= WBUFF, "chunk too big");

    const int tx = tid & 3;
    const int ty = tid >> 2;
    const int j0 = tx * 8;

    float bv[MT];
#pragma unroll
    for (int m = 0; m < MT; m++) bv[m] = __ldg(bias + chan<MT>(ty, m));

    ULL acc[4][MT];
#pragma unroll
    for (int t = 0; t < 4; t++)
#pragma unroll
        for (int m = 0; m < MT; m++) acc[t][m] = 0ull;

    __syncthreads();

    {
        const float4* src = reinterpret_cast<const float4*>(Wt);
        float4* dst = reinterpret_cast<float4*>(Ws);
#pragma unroll
        for (int i = tid; i < CHUNKF / 4; i += THREADS)
            cp_async16(smem_u32(dst + i), src + i);
        asm volatile("cp.async.commit_group;\n" ::: "memory");
    }

    for (int kb = 0; kb < NK; kb++) {
        asm volatile("cp.async.wait_group 0;\n" ::: "memory");
        __syncthreads();
        if (kb + 1 < NK) {
            const float4* src = reinterpret_cast<const float4*>(Wt + (kb + 1) * CHUNKF);
            float4* dst = reinterpret_cast<float4*>(Ws + ((kb + 1) & 1) * WBUFF);
#pragma unroll
            for (int i = tid; i < CHUNKF / 4; i += THREADS)
                cp_async16(smem_u32(dst + i), src + i);
            asm volatile("cp.async.commit_group;\n" ::: "memory");
        }

        const float* Wk  = Ws + (kb & 1) * WBUFF;
        const float* inb = IN + kb * KBT * LDA + j0;

#pragma unroll 8
        for (int kk = 0; kk < KBT; kk++) {
            float4 va = *reinterpret_cast<const float4*>(inb + kk * LDA);
            float4 vb = *reinterpret_cast<const float4*>(inb + kk * LDA + 4);
            if (PRE) {
                va.x = fmaxf(va.x, 0.f); va.y = fmaxf(va.y, 0.f);
                va.z = fmaxf(va.z, 0.f); va.w = fmaxf(va.w, 0.f);
                vb.x = fmaxf(vb.x, 0.f); vb.y = fmaxf(vb.y, 0.f);
                vb.z = fmaxf(vb.z, 0.f); vb.w = fmaxf(vb.w, 0.f);
            }
            ULL t0 = pack2(va.x, va.y), t1 = pack2(va.z, va.w);
            ULL t2 = pack2(vb.x, vb.y), t3 = pack2(vb.z, vb.w);
            float wf[MT];
            load_wf<MT>(Wk + kk * CW, ty, wf);
#pragma unroll
            for (int m = 0; m < MT; m++) {
                ULL wd = pack2(wf[m], wf[m]);
                fma2(acc[0][m], wd, t0);
                fma2(acc[1][m], wd, t1);
                fma2(acc[2][m], wd, t2);
                fma2(acc[3][m], wd, t3);
            }
        }
    }

    if (STAGE) __syncthreads();

#pragma unroll
    for (int m = 0; m < MT; m++) {
        float r[8];
        unpack2(acc[0][m], r[0], r[1]);
        unpack2(acc[1][m], r[2], r[3]);
        unpack2(acc[2][m], r[4], r[5]);
        unpack2(acc[3][m], r[6], r[7]);
        float* op = OUT + chan<MT>(ty, m) * LDA + j0;
        float4 o0, o1;
        o0.x = r[0] + bv[m]; o0.y = r[1] + bv[m];
        o0.z = r[2] + bv[m]; o0.w = r[3] + bv[m];
        o1.x = r[4] + bv[m]; o1.y = r[5] + bv[m];
        o1.z = r[6] + bv[m]; o1.w = r[7] + bv[m];
        if (RES) {
            float4 e0 = *reinterpret_cast<float4*>(op);
            float4 e1 = *reinterpret_cast<float4*>(op + 4);
            o0.x += e0.x; o0.y += e0.y; o0.z += e0.z; o0.w += e0.w;
            o1.x += e1.x; o1.y += e1.y; o1.z += e1.z; o1.w += e1.w;
        }
        if (POST) {
            o0.x = fmaxf(o0.x, 0.f); o0.y = fmaxf(o0.y, 0.f);
            o0.z = fmaxf(o0.z, 0.f); o0.w = fmaxf(o0.w, 0.f);
            o1.x = fmaxf(o1.x, 0.f); o1.y = fmaxf(o1.y, 0.f);
            o1.z = fmaxf(o1.z, 0.f); o1.w = fmaxf(o1.w, 0.f);
        }
        *reinterpret_cast<float4*>(op)     = o0;
        *reinterpret_cast<float4*>(op + 4) = o1;
    }
}

// ---------------- fused 1x1-conv layer (narrow: CW = 32 or 64) ----------------
// thread = MC channels x 4 tokens; 16 channel-groups x 8 token-groups.
// LDS floats per kk = 4 + MC  (vs 8 + CW/32 in wide mapping).
template<int CW, int KPAD, int KBT, bool PRE, bool POST, bool STAGE>
__device__ __noinline__ void conv_small(const float* __restrict__ Wt,
                                        const float* __restrict__ bias,
                                        const float* __restrict__ IN,
                                        float* __restrict__ OUT,
                                        float* __restrict__ Ws, int tid)
{
    constexpr int MC = CW / 16;          // 2 (CW=32) or 4 (CW=64)
    constexpr int NK = KPAD / KBT;
    constexpr int CHUNKF = KBT * CW;
    static_assert(CHUNKF <= WBUFF, "chunk too big");

    const int tx = tid & 7;
    const int ty = tid >> 3;             // 0..15
    const int j0 = tx * 4;
    const int ch0 = ty * MC;

    float bv[MC];
#pragma unroll
    for (int m = 0; m < MC; m++) bv[m] = __ldg(bias + ch0 + m);

    ULL acc[2][MC];
#pragma unroll
    for (int t = 0; t < 2; t++)
#pragma unroll
        for (int m = 0; m < MC; m++) acc[t][m] = 0ull;

    __syncthreads();

    {
        const float4* src = reinterpret_cast<const float4*>(Wt);
        float4* dst = reinterpret_cast<float4*>(Ws);
#pragma unroll
        for (int i = tid; i < CHUNKF / 4; i += THREADS)
            cp_async16(smem_u32(dst + i), src + i);
        asm volatile("cp.async.commit_group;\n" ::: "memory");
    }

    for (int kb = 0; kb < NK; kb++) {
        asm volatile("cp.async.wait_group 0;\n" ::: "memory");
        __syncthreads();
        if (kb + 1 < NK) {
            const float4* src = reinterpret_cast<const float4*>(Wt + (kb + 1) * CHUNKF);
            float4* dst = reinterpret_cast<float4*>(Ws + ((kb + 1) & 1) * WBUFF);
#pragma unroll
            for (int i = tid; i < CHUNKF / 4; i += THREADS)
                cp_async16(smem_u32(dst + i), src + i);
            asm volatile("cp.async.commit_group;\n" ::: "memory");
        }

        const float* Wk  = Ws + (kb & 1) * WBUFF;
        const float* inb = IN + kb * KBT * LDA + j0;

#pragma unroll 8
        for (int kk = 0; kk < KBT; kk++) {
            float4 v = *reinterpret_cast<const float4*>(inb + kk * LDA);
            if (PRE) {
                v.x = fmaxf(v.x, 0.f); v.y = fmaxf(v.y, 0.f);
                v.z = fmaxf(v.z, 0.f); v.w = fmaxf(v.w, 0.f);
            }
            ULL t0 = pack2(v.x, v.y), t1 = pack2(v.z, v.w);
            float wf[MC];
            if constexpr (MC == 4) {
                float4 a = *reinterpret_cast<const float4*>(Wk + kk * CW + ch0);
                wf[0] = a.x; wf[1] = a.y; wf[2] = a.z; wf[3] = a.w;
            } else {
                float2 a = *reinterpret_cast<const float2*>(Wk + kk * CW + ch0);
                wf[0] = a.x; wf[1] = a.y;
            }
#pragma unroll
            for (int m = 0; m < MC; m++) {
                ULL wd = pack2(wf[m], wf[m]);
                fma2(acc[0][m], wd, t0);
                fma2(acc[1][m], wd, t1);
            }
        }
    }

    if (STAGE) __syncthreads();

#pragma unroll
    for (int m = 0; m < MC; m++) {
        float4 o;
        unpack2(acc[0][m], o.x, o.y);
        unpack2(acc[1][m], o.z, o.w);
        o.x += bv[m]; o.y += bv[m]; o.z += bv[m]; o.w += bv[m];
        if (POST) {
            o.x = fmaxf(o.x, 0.f); o.y = fmaxf(o.y, 0.f);
            o.z = fmaxf(o.z, 0.f); o.w = fmaxf(o.w, 0.f);
        }
        *reinterpret_cast<float4*>(OUT + (ch0 + m) * LDA + j0) = o;
    }
}

#define LCONV(L, CW, KPAD, KBT, PRE, POST, RES, STAGE, INB, OUTB) \
    conv_layer<CW, KPAD, KBT, PRE, POST, RES, STAGE>(g_Wt + c_layers[L][6], g_bias + c_layers[L][7], INB, OUTB, Ws, tid)
#define LCONVS(L, CW, KPAD, KBT, PRE, POST, STAGE, INB, OUTB) \
    conv_small<CW, KPAD, KBT, PRE, POST, STAGE>(g_Wt + c_layers[L][6], g_bias + c_layers[L][7], INB, OUTB, Ws, tid)

// ---------------- main fused kernel ----------------
__global__ void __launch_bounds__(THREADS, 3) vqvae_kernel(Params P)
{
    extern __shared__ float sm[];
    float* A    = sm + SM_A;
    float* T32  = A + 256 * LDA;
    float* Ws   = sm + SM_W;
    float* cand_d = sm + SM_AUX;
    float* cand_i = cand_d + 128;
    float* ibest  = cand_i + 128;
    float* wsum   = ibest + 32;

    const int tid = threadIdx.x;
    const int n0  = blockIdx.x * TILE;

    for (int idx = tid; idx < 176 * TILE; idx += THREADS) {
        int c = idx >> 5;
        int j = idx & 31;
        A[c * LDA + j] = g_X[c * NTOK + n0 + j];
    }

    // ---- encoder ----
    LCONV (0, 128, 176, 16, false, true,  false, true,  A,   A  );
    LCONV (1, 256, 128, 16, false, true,  false, true,  A,   A  );
    LCONV (2, 256, 256, 16, false, false, false, true,  A,   A  );
    LCONVS(3,  32, 256, 128, true, true,  false, A,   T32);
    LCONV (4, 256,  32, 16, false, false, true,  false, T32, A  );
    LCONVS(5,  32, 256, 128, true, true,  false, A,   T32);
    LCONV (6, 256,  32, 16, false, false, true,  false, T32, A  );
    LCONVS(7,  64, 256, 64, true,  false, true,  A,   A  );   // z -> rows 0..63

    // ---- vector quantize ----
    {
        const float* embed = P.in[17];
        const int l = tid & 31;
        const int w = tid >> 5;
        const int cgrp = l >> 2;
        const int jgrp = l & 3;
        const int j0v = jgrp * 8;

        __syncthreads();

        float best[8]; int bidx[8];
#pragma unroll
        for (int t = 0; t < 8; t++) { best[t] = 3.4e38f; bidx[t] = 0; }

#pragma unroll
        for (int cbi = 0; cbi < 2; cbi++) {
            const int cb = w * 2 + cbi;
            const int cbase = cb * 64 + cgrp * 8;

            ULL acc[4][8];
#pragma unroll
            for (int c2 = 0; c2 < 4; c2++)
#pragma unroll
                for (int t = 0; t < 8; t++) acc[c2][t] = 0ull;

#pragma unroll 8
            for (int d = 0; d < EDIM; d++) {
                const float* zr = A + d * LDA + j0v;
                float4 za = *reinterpret_cast<const float4*>(zr);
                float4 zb = *reinterpret_cast<const float4*>(zr + 4);
                ULL zd[8];
                zd[0] = pack2(za.x, za.x); zd[1] = pack2(za.y, za.y);
                zd[2] = pack2(za.z, za.z); zd[3] = pack2(za.w, za.w);
                zd[4] = pack2(zb.x, zb.x); zd[5] = pack2(zb.y, zb.y);
                zd[6] = pack2(zb.z, zb.z); zd[7] = pack2(zb.w, zb.w);
                const ulonglong2* ep =
                    reinterpret_cast<const ulonglong2*>(embed + d * NEMB + cbase);
                ulonglong2 e01 = __ldg(ep), e23 = __ldg(ep + 1);
                ULL ec[4] = {e01.x, e01.y, e23.x, e23.y};
#pragma unroll
                for (int c2 = 0; c2 < 4; c2++)
#pragma unroll
                    for (int t = 0; t < 8; t++)
                        fma2(acc[c2][t], ec[c2], zd[t]);
            }

            float4 en0 = __ldg(reinterpret_cast<const float4*>(g_enorm + cbase));
            float4 en1 = __ldg(reinterpret_cast<const float4*>(g_enorm + cbase + 4));
            float en[8] = {en0.x, en0.y, en0.z, en0.w, en1.x, en1.y, en1.z, en1.w};
#pragma unroll
            for (int c2 = 0; c2 < 4; c2++) {
                int c = cbase + c2 * 2;
#pragma unroll
                for (int t = 0; t < 8; t++) {
                    float d0, d1; unpack2(acc[c2][t], d0, d1);
                    float s0 = en[c2 * 2]     - 2.f * d0;
                    float s1 = en[c2 * 2 + 1] - 2.f * d1;
                    if (s0 < best[t]) { best[t] = s0; bidx[t] = c; }
                    if (s1 < best[t]) { best[t] = s1; bidx[t] = c + 1; }
                }
            }
        }

#pragma unroll
        for (int off = 4; off < 32; off <<= 1) {
#pragma unroll
            for (int t = 0; t < 8; t++) {
                float ob = __shfl_xor_sync(0xffffffffu, best[t], off);
                int   oi = __shfl_xor_sync(0xffffffffu, bidx[t], off);
                if (ob < best[t] || (ob == best[t] && oi < bidx[t])) {
                    best[t] = ob; bidx[t] = oi;
                }
            }
        }
        if (cgrp == 0) {
#pragma unroll
            for (int t = 0; t < 8; t++) {
                cand_d[w * 32 + j0v + t] = best[t];
                reinterpret_cast<int*>(cand_i)[w * 32 + j0v + t] = bidx[t];
            }
        }
        __syncthreads();
        if (tid < 32) {
            float bb = cand_d[tid];
            int   bi = reinterpret_cast<int*>(cand_i)[tid];
#pragma unroll
            for (int ww = 1; ww < 4; ww++) {
                float ob = cand_d[ww * 32 + tid];
                int   oi = reinterpret_cast<int*>(cand_i)[ww * 32 + tid];
                if (ob < bb || (ob == bb && oi < bi)) { bb = ob; bi = oi; }
            }
            reinterpret_cast<int*>(ibest)[tid] = bi;
        }
        __syncthreads();

        const int j = tid >> 2;
        const int q = tid & 3;
        const int bsel = reinterpret_cast<int*>(ibest)[j];
        float dsum = 0.f;
#pragma unroll
        for (int dd = 0; dd < 16; dd++) {
            int d = q * 16 + dd;
            float e = __ldg(embed + d * NEMB + bsel);
            float z = A[d * LDA + j];
            A[d * LDA + j] = e;
            float df = e - z;
            dsum += df * df;
        }
#pragma unroll
        for (int off = 16; off > 0; off >>= 1)
            dsum += __shfl_xor_sync(0xffffffffu, dsum, off);
        if ((tid & 31) == 0) wsum[tid >> 5] = dsum;
        __syncthreads();
        if (tid == 0)
            g_part[blockIdx.x] = wsum[0] + wsum[1] + wsum[2] + wsum[3];
    }

    // ---- decoder ----
    LCONV (8, 256,  64, 16, false, false, false, true,  A,   A  );
    LCONVS(9,  32, 256, 128, true, true,  false, A,   T32);
    LCONV (10, 256, 32, 16, false, false, true,  false, T32, A  );
    LCONVS(11, 32, 256, 128, true, true,  false, A,   T32);
    LCONV (12, 256, 32, 16, false, false, true,  false, T32, A  );
    LCONV (13, 128, 256, 32, true, true,  false, true,  A,   A  );
    LCONV (14, 192, 128, 16, false, false, false, true,  A,   A  );
    __syncthreads();

    for (int idx = tid; idx < CINN * TILE; idx += THREADS) {
        int c = idx >> 5;
        int j = idx & 31;
        if (c < CINN) g_O[c * NTOK + n0 + j] = A[c * LDA + j];
    }

    // ---- last-block finalize of diff ----
    __threadfence();
    __shared__ unsigned int is_last;
    if (tid == 0) is_last = (atomicAdd(&g_count, 1u) == NBLK - 1) ? 1u : 0u;
    __syncthreads();
    if (is_last) {
        float s = 0.f;
        for (int i = tid; i < NBLK; i += THREADS) s += g_part[i];
#pragma unroll
        for (int off = 16; off > 0; off >>= 1)
            s += __shfl_xor_sync(0xffffffffu, s, off);
        if ((tid & 31) == 0) wsum[tid >> 5] = s;
        __syncthreads();
        if (tid == 0) {
            float t = wsum[0] + wsum[1] + wsum[2] + wsum[3];
            if (P.out_size > DEC_ELEMS)
                P.out[DEC_ELEMS] = t * (1.0f / 8388608.0f);
            g_count = 0u;
        }
    }
}

// ---------------- launch ----------------
extern "C" void kernel_launch(void* const* d_in, const int* in_sizes, int n_in,
                              void* d_out, int out_size)
{
    (void)in_sizes; (void)n_in;
    Params P;
    for (int i = 0; i < 32; i++) P.in[i] = (const float*)d_in[i];
    P.out = (float*)d_out;
    P.out_size = out_size;

    static bool attr_set = false;
    if (!attr_set) {
        cudaFuncSetAttribute(vqvae_kernel, cudaFuncAttributeMaxDynamicSharedMemorySize, SMEM_BYTES);
        attr_set = true;
    }
    prep_kernel<<<16, 256>>>(P);
    prep_x<<<dim3(NTOK / 32, 6), dim3(32, 8)>>>(P);
    vqvae_kernel<<<NBLK, THREADS, SMEM_BYTES>>>(P);
    post_out<<<dim3(NTOK / 32, 6), dim3(32, 8)>>>(P);
}

// round 15
// speedup vs baseline: 2.1017x; 1.0843x over previous
#include <cuda_runtime.h>
#include <cstdint>

// ---------------- problem constants ----------------
#define BN   32
#define TN   4096
#define CINN 165
#define EDIM 64
#define NEMB 512
#define NTOK (BN*TN)          // 131072
#define TILE 32               // tokens per CTA
#define NBLK (NTOK/TILE)      // 4096
#define LDA  32               // token-row stride (floats) = 128B aligned
#define DEC_ELEMS (NTOK*CINN) // 21626880
#define THREADS 128

// shared layout (floats)
#define AROWS  288
#define SM_A   0
#define SM_W   (AROWS*LDA)          // 9216
#define WBUFF  4096
#define SM_AUX (SM_W + 2*WBUFF)     // 17408
#define SM_FLOATS (SM_AUX + 304)
#define SMEM_BYTES (SM_FLOATS*4)    // ~70.8 KB -> 3 CTAs/SM

typedef unsigned long long ULL;

__device__ float g_Wt[276480];
__device__ float g_bias[2432];
__device__ float g_enorm[NEMB];
__device__ float g_part[NBLK];
__device__ unsigned int g_count;

// layer metadata: {w_in_idx, b_in_idx, CIN, COUT, KPAD, CW, woff, boff}
__constant__ int c_layers[15][8] = {
    { 1,  2, 165, 128, 176, 128,      0,    0},
    { 3,  4, 128, 256, 128, 256,  22528,  128},
    { 5,  6, 256, 256, 256, 256,  55296,  384},
    { 7,  8, 256,  32, 256,  32, 120832,  640},
    { 9, 10,  32, 256,  32, 256, 129024,  672},
    {11, 12, 256,  32, 256,  32, 137216,  928},
    {13, 14,  32, 256,  32, 256, 145408,  960},
    {15, 16, 256,  64, 256,  64, 153600, 1216},
    {18, 19,  64, 256,  64, 256, 169984, 1280},
    {20, 21, 256,  32, 256,  32, 186368, 1536},
    {22, 23,  32, 256,  32, 256, 194560, 1568},
    {24, 25, 256,  32, 256,  32, 202752, 1824},
    {26, 27,  32, 256,  32, 256, 210944, 1856},
    {28, 29, 256, 128, 256, 128, 219136, 2112},
    {30, 31, 128, 165, 128, 192, 251904, 2240},
};

// ---------------- f32x2 helpers ----------------
__device__ __forceinline__ ULL pack2(float x, float y) {
    ULL r; asm("mov.b64 %0, {%1, %2};" : "=l"(r) : "f"(x), "f"(y)); return r;
}
__device__ __forceinline__ void unpack2(ULL v, float& x, float& y) {
    asm("mov.b64 {%0, %1}, %2;" : "=f"(x), "=f"(y) : "l"(v));
}
__device__ __forceinline__ void fma2(ULL& d, ULL a, ULL b) {
    asm("fma.rn.f32x2 %0, %1, %2, %0;" : "+l"(d) : "l"(a), "l"(b));
}
__device__ __forceinline__ uint32_t smem_u32(const void* p) {
    uint32_t a;
    asm("{ .reg .u64 t; cvta.to.shared.u64 t, %1; cvt.u32.u64 %0, t; }" : "=r"(a) : "l"(p));
    return a;
}
__device__ __forceinline__ void cp_async16(uint32_t dst, const void* src) {
    asm volatile("cp.async.cg.shared.global [%0], [%1], 16;\n" :: "r"(dst), "l"(src));
}

struct Params { const float* in[32]; float* out; int out_size; };

// ---------------- prep: weights transpose+pad, codebook norms ----------------
__global__ void prep_kernel(Params P) {
    const int L = blockIdx.x;
    if (L == 15) {
        const float* embed = P.in[17];
        for (int k = threadIdx.x; k < NEMB; k += blockDim.x) {
            float s = 0.f;
            for (int d = 0; d < EDIM; d++) { float e = embed[d * NEMB + k]; s += e * e; }
            g_enorm[k] = s;
        }
        return;
    }
    const int CIN  = c_layers[L][2], COUT = c_layers[L][3];
    const int KPAD = c_layers[L][4], CW   = c_layers[L][5];
    const int woff = c_layers[L][6], boff = c_layers[L][7];
    const float* W = P.in[c_layers[L][0]];
    const float* b = P.in[c_layers[L][1]];
    for (int e = threadIdx.x; e < KPAD * CW; e += blockDim.x) {
        int k = e / CW, c = e - (e / CW) * CW;
        float v = (k < CIN && c < COUT) ? W[c * CIN + k] : 0.f;
        g_Wt[woff + e] = v;
    }
    for (int c = threadIdx.x; c < CW; c += blockDim.x)
        g_bias[boff + c] = (c < COUT) ? b[c] : 0.f;
}

// ---------------- channel ownership (bank-conflict-free quads) ----------------
template<int MT>
__device__ __forceinline__ int chan(int ty, int m) {
    if constexpr (MT == 8) return (m < 4) ? ty * 4 + m : 128 + ty * 4 + (m - 4);
    else if constexpr (MT == 6) return (m < 4) ? ty * 4 + m : 128 + ty * 2 + (m - 4);
    else if constexpr (MT == 4) return ty * 4 + m;
    else return ty;
}

template<int MT>
__device__ __forceinline__ void load_wf(const float* Wrow, int ty, float* wf) {
    if constexpr (MT == 8) {
        float4 a = *reinterpret_cast<const float4*>(Wrow + ty * 4);
        float4 b = *reinterpret_cast<const float4*>(Wrow + 128 + ty * 4);
        wf[0] = a.x; wf[1] = a.y; wf[2] = a.z; wf[3] = a.w;
        wf[4] = b.x; wf[5] = b.y; wf[6] = b.z; wf[7] = b.w;
    } else if constexpr (MT == 6) {
        float4 a = *reinterpret_cast<const float4*>(Wrow + ty * 4);
        float2 b = *reinterpret_cast<const float2*>(Wrow + 128 + ty * 2);
        wf[0] = a.x; wf[1] = a.y; wf[2] = a.z; wf[3] = a.w;
        wf[4] = b.x; wf[5] = b.y;
    } else if constexpr (MT == 4) {
        float4 a = *reinterpret_cast<const float4*>(Wrow + ty * 4);
        wf[0] = a.x; wf[1] = a.y; wf[2] = a.z; wf[3] = a.w;
    }
}

// ---------------- fused 1x1-conv layer (wide channels: CW >= 128) ----------------
template<int CW, int KPAD, int KBT, bool PRE, bool POST, bool RES, bool STAGE>
__device__ __noinline__ void conv_layer(const float* __restrict__ Wt,
                                        const float* __restrict__ bias,
                                        const float* __restrict__ IN,
                                        float* __restrict__ OUT,
                                        float* __restrict__ Ws, int tid)
{
    constexpr int MT = CW / 32;
    constexpr int NK = KPAD / KBT;
    constexpr int CHUNKF = KBT * CW;
    static_assert(CHUNKF <= WBUFF, "chunk too big");

    const int tx = tid & 3;
    const int ty = tid >> 2;
    const int j0 = tx * 8;

    float bv[MT];
#pragma unroll
    for (int m = 0; m < MT; m++) bv[m] = __ldg(bias + chan<MT>(ty, m));

    ULL acc[4][MT];
#pragma unroll
    for (int t = 0; t < 4; t++)
#pragma unroll
        for (int m = 0; m < MT; m++) acc[t][m] = 0ull;

    __syncthreads();

    {
        const float4* src = reinterpret_cast<const float4*>(Wt);
        float4* dst = reinterpret_cast<float4*>(Ws);
#pragma unroll
        for (int i = tid; i < CHUNKF / 4; i += THREADS)
            cp_async16(smem_u32(dst + i), src + i);
        asm volatile("cp.async.commit_group;\n" ::: "memory");
    }

    for (int kb = 0; kb < NK; kb++) {
        asm volatile("cp.async.wait_group 0;\n" ::: "memory");
        __syncthreads();
        if (kb + 1 < NK) {
            const float4* src = reinterpret_cast<const float4*>(Wt + (kb + 1) * CHUNKF);
            float4* dst = reinterpret_cast<float4*>(Ws + ((kb + 1) & 1) * WBUFF);
#pragma unroll
            for (int i = tid; i < CHUNKF / 4; i += THREADS)
                cp_async16(smem_u32(dst + i), src + i);
            asm volatile("cp.async.commit_group;\n" ::: "memory");
        }

        const float* Wk  = Ws + (kb & 1) * WBUFF;
        const float* inb = IN + kb * KBT * LDA + j0;

#pragma unroll 8
        for (int kk = 0; kk < KBT; kk++) {
            float4 va = *reinterpret_cast<const float4*>(inb + kk * LDA);
            float4 vb = *reinterpret_cast<const float4*>(inb + kk * LDA + 4);
            if (PRE) {
                va.x = fmaxf(va.x, 0.f); va.y = fmaxf(va.y, 0.f);
                va.z = fmaxf(va.z, 0.f); va.w = fmaxf(va.w, 0.f);
                vb.x = fmaxf(vb.x, 0.f); vb.y = fmaxf(vb.y, 0.f);
                vb.z = fmaxf(vb.z, 0.f); vb.w = fmaxf(vb.w, 0.f);
            }
            ULL t0 = pack2(va.x, va.y), t1 = pack2(va.z, va.w);
            ULL t2 = pack2(vb.x, vb.y), t3 = pack2(vb.z, vb.w);
            float wf[MT];
            load_wf<MT>(Wk + kk * CW, ty, wf);
#pragma unroll
            for (int m = 0; m < MT; m++) {
                ULL wd = pack2(wf[m], wf[m]);
                fma2(acc[0][m], wd, t0);
                fma2(acc[1][m], wd, t1);
                fma2(acc[2][m], wd, t2);
                fma2(acc[3][m], wd, t3);
            }
        }
    }

    if (STAGE) __syncthreads();

#pragma unroll
    for (int m = 0; m < MT; m++) {
        float r[8];
        unpack2(acc[0][m], r[0], r[1]);
        unpack2(acc[1][m], r[2], r[3]);
        unpack2(acc[2][m], r[4], r[5]);
        unpack2(acc[3][m], r[6], r[7]);
        float* op = OUT + chan<MT>(ty, m) * LDA + j0;
        float4 o0, o1;
        o0.x = r[0] + bv[m]; o0.y = r[1] + bv[m];
        o0.z = r[2] + bv[m]; o0.w = r[3] + bv[m];
        o1.x = r[4] + bv[m]; o1.y = r[5] + bv[m];
        o1.z = r[6] + bv[m]; o1.w = r[7] + bv[m];
        if (RES) {
            float4 e0 = *reinterpret_cast<float4*>(op);
            float4 e1 = *reinterpret_cast<float4*>(op + 4);
            o0.x += e0.x; o0.y += e0.y; o0.z += e0.z; o0.w += e0.w;
            o1.x += e1.x; o1.y += e1.y; o1.z += e1.z; o1.w += e1.w;
        }
        if (POST) {
            o0.x = fmaxf(o0.x, 0.f); o0.y = fmaxf(o0.y, 0.f);
            o0.z = fmaxf(o0.z, 0.f); o0.w = fmaxf(o0.w, 0.f);
            o1.x = fmaxf(o1.x, 0.f); o1.y = fmaxf(o1.y, 0.f);
            o1.z = fmaxf(o1.z, 0.f); o1.w = fmaxf(o1.w, 0.f);
        }
        *reinterpret_cast<float4*>(op)     = o0;
        *reinterpret_cast<float4*>(op + 4) = o1;
    }
}

// ---------------- fused 1x1-conv layer (narrow: CW = 32 or 64, k-split) ----------------
// k-split across warps: CW=32 -> 4 segments (1 warp each); CW=64 -> 2 segments (2 warps).
// Lane = 4 channels x 8 tokens. Weights via coalesced __ldg (L1-cached, no smem stage).
// Partials accumulated per segment in padded Ws rows (stride 33), reduced after barrier.
template<int CW, int KPAD, bool PRE, bool POST>
__device__ __noinline__ void conv_small(const float* __restrict__ Wt,
                                        const float* __restrict__ bias,
                                        const float* __restrict__ IN,
                                        float* __restrict__ OUT,
                                        float* __restrict__ Ws, int tid)
{
    constexpr int KS   = (CW == 32) ? 4 : 2;
    constexpr int KLEN = KPAD / KS;
    constexpr int PROW = CW * 33;          // padded partial block per segment
    static_assert(KS * PROW <= 2 * WBUFF, "partials too big");

    const int w = tid >> 5, l = tid & 31;
    const int ks  = (CW == 32) ? w : (w >> 1);
    const int chg = (CW == 32) ? (l & 7) : (((w & 1) << 3) | (l & 7));
    const int tg  = l >> 3;
    const int j0  = tg * 8;
    const int ch0 = chg * 4;
    const int k0  = ks * KLEN;

    ULL acc[4][4];
#pragma unroll
    for (int t = 0; t < 4; t++)
#pragma unroll
        for (int m = 0; m < 4; m++) acc[t][m] = 0ull;

    __syncthreads();   // entry: prev writes visible; Ws free

#pragma unroll 8
    for (int kk = 0; kk < KLEN; kk++) {
        int k = k0 + kk;
        const float* inr = IN + k * LDA + j0;
        float4 va = *reinterpret_cast<const float4*>(inr);
        float4 vb = *reinterpret_cast<const float4*>(inr + 4);
        if (PRE) {
            va.x = fmaxf(va.x, 0.f); va.y = fmaxf(va.y, 0.f);
            va.z = fmaxf(va.z, 0.f); va.w = fmaxf(va.w, 0.f);
            vb.x = fmaxf(vb.x, 0.f); vb.y = fmaxf(vb.y, 0.f);
            vb.z = fmaxf(vb.z, 0.f); vb.w = fmaxf(vb.w, 0.f);
        }
        ULL t0 = pack2(va.x, va.y), t1 = pack2(va.z, va.w);
        ULL t2 = pack2(vb.x, vb.y), t3 = pack2(vb.z, vb.w);
        float4 wq = __ldg(reinterpret_cast<const float4*>(Wt + k * CW + ch0));
        float wf[4] = {wq.x, wq.y, wq.z, wq.w};
#pragma unroll
        for (int m = 0; m < 4; m++) {
            ULL wd = pack2(wf[m], wf[m]);
            fma2(acc[0][m], wd, t0);
            fma2(acc[1][m], wd, t1);
            fma2(acc[2][m], wd, t2);
            fma2(acc[3][m], wd, t3);
        }
    }

    // partial store (padded rows, stride 33 -> conflict-light)
    float* Pp = Ws + ks * PROW;
#pragma unroll
    for (int m = 0; m < 4; m++) {
        float r[8];
        unpack2(acc[0][m], r[0], r[1]);
        unpack2(acc[1][m], r[2], r[3]);
        unpack2(acc[2][m], r[4], r[5]);
        unpack2(acc[3][m], r[6], r[7]);
        float* pp = Pp + (ch0 + m) * 33 + j0;
#pragma unroll
        for (int n = 0; n < 8; n++) pp[n] = r[n];
    }
    __syncthreads();   // partials visible; also: all IN reads complete (in-place safe)

    // reduce: CW*32 outputs, CW/4 per thread
    constexpr int NO = CW * 32 / THREADS;
#pragma unroll
    for (int i = 0; i < NO; i++) {
        int o = tid * NO + i;
        int ch = o >> 5, j = o & 31;
        float s = 0.f;
#pragma unroll
        for (int q = 0; q < KS; q++) s += Ws[q * PROW + ch * 33 + j];
        s += __ldg(bias + ch);
        if (POST) s = fmaxf(s, 0.f);
        OUT[ch * LDA + j] = s;
    }
}

#define LCONV(L, CW, KPAD, KBT, PRE, POST, RES, STAGE, INB, OUTB) \
    conv_layer<CW, KPAD, KBT, PRE, POST, RES, STAGE>(g_Wt + c_layers[L][6], g_bias + c_layers[L][7], INB, OUTB, Ws, tid)
#define LCONVS(L, CW, KPAD, PRE, POST, INB, OUTB) \
    conv_small<CW, KPAD, PRE, POST>(g_Wt + c_layers[L][6], g_bias + c_layers[L][7], INB, OUTB, Ws, tid)

// ---------------- main fused kernel ----------------
__global__ void __launch_bounds__(THREADS, 3) vqvae_kernel(Params P)
{
    extern __shared__ float sm[];
    float* A    = sm + SM_A;
    float* T32  = A + 256 * LDA;
    float* Ws   = sm + SM_W;
    float* cand_d = sm + SM_AUX;
    float* cand_i = cand_d + 128;
    float* ibest  = cand_i + 128;
    float* wsum   = ibest + 32;

    const int tid = threadIdx.x;
    const int n0  = blockIdx.x * TILE;

    // ---- input: coalesced gmem read -> padded Ws tile -> conflict-free A write ----
    {
        const float* x = P.in[0];
        for (int idx = tid; idx < 176 * TILE; idx += THREADS) {
            int j = idx / 176;
            int c = idx - j * 176;
            Ws[j * 177 + c] = (c < CINN) ? x[(n0 + j) * CINN + c] : 0.f;
        }
        __syncthreads();
        for (int idx = tid; idx < 176 * TILE; idx += THREADS) {
            int c = idx >> 5;
            int j = idx & 31;
            A[c * LDA + j] = Ws[j * 177 + c];
        }
        // next layer's entry barrier orders these writes + frees Ws
    }

    // ---- encoder ----
    LCONV (0, 128, 176, 16, false, true,  false, true,  A,   A  );
    LCONV (1, 256, 128, 16, false, true,  false, true,  A,   A  );
    LCONV (2, 256, 256, 16, false, false, false, true,  A,   A  );
    LCONVS(3,  32, 256, true, true,  A,   T32);
    LCONV (4, 256,  32, 16, false, false, true,  false, T32, A  );
    LCONVS(5,  32, 256, true, true,  A,   T32);
    LCONV (6, 256,  32, 16, false, false, true,  false, T32, A  );
    LCONVS(7,  64, 256, true, false, A,   A  );   // z -> rows 0..63

    // ---- vector quantize ----
    {
        const float* embed = P.in[17];
        const int l = tid & 31;
        const int w = tid >> 5;
        const int cgrp = l >> 2;
        const int jgrp = l & 3;
        const int j0v = jgrp * 8;

        __syncthreads();

        float best[8]; int bidx[8];
#pragma unroll
        for (int t = 0; t < 8; t++) { best[t] = 3.4e38f; bidx[t] = 0; }

#pragma unroll
        for (int cbi = 0; cbi < 2; cbi++) {
            const int cb = w * 2 + cbi;
            const int cbase = cb * 64 + cgrp * 8;

            ULL acc[4][8];
#pragma unroll
            for (int c2 = 0; c2 < 4; c2++)
#pragma unroll
                for (int t = 0; t < 8; t++) acc[c2][t] = 0ull;

#pragma unroll 8
            for (int d = 0; d < EDIM; d++) {
                const float* zr = A + d * LDA + j0v;
                float4 za = *reinterpret_cast<const float4*>(zr);
                float4 zb = *reinterpret_cast<const float4*>(zr + 4);
                ULL zd[8];
                zd[0] = pack2(za.x, za.x); zd[1] = pack2(za.y, za.y);
                zd[2] = pack2(za.z, za.z); zd[3] = pack2(za.w, za.w);
                zd[4] = pack2(zb.x, zb.x); zd[5] = pack2(zb.y, zb.y);
                zd[6] = pack2(zb.z, zb.z); zd[7] = pack2(zb.w, zb.w);
                const ulonglong2* ep =
                    reinterpret_cast<const ulonglong2*>(embed + d * NEMB + cbase);
                ulonglong2 e01 = __ldg(ep), e23 = __ldg(ep + 1);
                ULL ec[4] = {e01.x, e01.y, e23.x, e23.y};
#pragma unroll
                for (int c2 = 0; c2 < 4; c2++)
#pragma unroll
                    for (int t = 0; t < 8; t++)
                        fma2(acc[c2][t], ec[c2], zd[t]);
            }

            float4 en0 = __ldg(reinterpret_cast<const float4*>(g_enorm + cbase));
            float4 en1 = __ldg(reinterpret_cast<const float4*>(g_enorm + cbase + 4));
            float en[8] = {en0.x, en0.y, en0.z, en0.w, en1.x, en1.y, en1.z, en1.w};
#pragma unroll
            for (int c2 = 0; c2 < 4; c2++) {
                int c = cbase + c2 * 2;
#pragma unroll
                for (int t = 0; t < 8; t++) {
                    float d0, d1; unpack2(acc[c2][t], d0, d1);
                    float s0 = en[c2 * 2]     - 2.f * d0;
                    float s1 = en[c2 * 2 + 1] - 2.f * d1;
                    if (s0 < best[t]) { best[t] = s0; bidx[t] = c; }
                    if (s1 < best[t]) { best[t] = s1; bidx[t] = c + 1; }
                }
            }
        }

#pragma unroll
        for (int off = 4; off < 32; off <<= 1) {
#pragma unroll
            for (int t = 0; t < 8; t++) {
                float ob = __shfl_xor_sync(0xffffffffu, best[t], off);
                int   oi = __shfl_xor_sync(0xffffffffu, bidx[t], off);
                if (ob < best[t] || (ob == best[t] && oi < bidx[t])) {
                    best[t] = ob; bidx[t] = oi;
                }
            }
        }
        if (cgrp == 0) {
#pragma unroll
            for (int t = 0; t < 8; t++) {
                cand_d[w * 32 + j0v + t] = best[t];
                reinterpret_cast<int*>(cand_i)[w * 32 + j0v + t] = bidx[t];
            }
        }
        __syncthreads();
        if (tid < 32) {
            float bb = cand_d[tid];
            int   bi = reinterpret_cast<int*>(cand_i)[tid];
#pragma unroll
            for (int ww = 1; ww < 4; ww++) {
                float ob = cand_d[ww * 32 + tid];
                int   oi = reinterpret_cast<int*>(cand_i)[ww * 32 + tid];
                if (ob < bb || (ob == bb && oi < bi)) { bb = ob; bi = oi; }
            }
            reinterpret_cast<int*>(ibest)[tid] = bi;
        }
        __syncthreads();

        const int j = tid >> 2;
        const int q = tid & 3;
        const int bsel = reinterpret_cast<int*>(ibest)[j];
        float dsum = 0.f;
#pragma unroll
        for (int dd = 0; dd < 16; dd++) {
            int d = q * 16 + dd;
            float e = __ldg(embed + d * NEMB + bsel);
            float z = A[d * LDA + j];
            A[d * LDA + j] = e;
            float df = e - z;
            dsum += df * df;
        }
#pragma unroll
        for (int off = 16; off > 0; off >>= 1)
            dsum += __shfl_xor_sync(0xffffffffu, dsum, off);
        if ((tid & 31) == 0) wsum[tid >> 5] = dsum;
        __syncthreads();
        if (tid == 0)
            g_part[blockIdx.x] = wsum[0] + wsum[1] + wsum[2] + wsum[3];
    }

    // ---- decoder ----
    LCONV (8, 256,  64, 16, false, false, false, true,  A,   A  );
    LCONVS(9,  32, 256, true, true,  A,   T32);
    LCONV (10, 256, 32, 16, false, false, true,  false, T32, A  );
    LCONVS(11, 32, 256, true, true,  A,   T32);
    LCONV (12, 256, 32, 16, false, false, true,  false, T32, A  );
    LCONV (13, 128, 256, 32, true, true,  false, true,  A,   A  );
    LCONV (14, 192, 128, 16, false, false, false, true,  A,   A  );
    __syncthreads();   // A final; Ws free

    // ---- output: conflict-free A read -> padded Ws tile -> coalesced gmem write ----
    {
        for (int idx = tid; idx < CINN * 32; idx += THREADS) {
            int c = idx >> 5;
            int j = idx & 31;
            Ws[j * 167 + c] = A[c * LDA + j];
        }
        __syncthreads();
        for (int idx = tid; idx < CINN * TILE; idx += THREADS) {
            int j = idx / CINN;
            int c = idx - j * CINN;
            P.out[(n0 + j) * CINN + c] = Ws[j * 167 + c];
        }
    }

    // ---- last-block finalize of diff ----
    __threadfence();
    __shared__ unsigned int is_last;
    if (tid == 0) is_last = (atomicAdd(&g_count, 1u) == NBLK - 1) ? 1u : 0u;
    __syncthreads();
    if (is_last) {
        float s = 0.f;
        for (int i = tid; i < NBLK; i += THREADS) s += g_part[i];
#pragma unroll
        for (int off = 16; off > 0; off >>= 1)
            s += __shfl_xor_sync(0xffffffffu, s, off);
        if ((tid & 31) == 0) wsum[tid >> 5] = s;
        __syncthreads();
        if (tid == 0) {
            float t = wsum[0] + wsum[1] + wsum[2] + wsum[3];
            if (P.out_size > DEC_ELEMS)
                P.out[DEC_ELEMS] = t * (1.0f / 8388608.0f);
            g_count = 0u;
        }
    }
}

// ---------------- launch ----------------
extern "C" void kernel_launch(void* const* d_in, const int* in_sizes, int n_in,
                              void* d_out, int out_size)
{
    (void)in_sizes; (void)n_in;
    Params P;
    for (int i = 0; i < 32; i++) P.in[i] = (const float*)d_in[i];
    P.out = (float*)d_out;
    P.out_size = out_size;

    static bool attr_set = false;
    if (!attr_set) {
        cudaFuncSetAttribute(vqvae_kernel, cudaFuncAttributeMaxDynamicSharedMemorySize, SMEM_BYTES);
        attr_set = true;
    }
    prep_kernel<<<16, 256>>>(P);
    vqvae_kernel<<<NBLK, THREADS, SMEM_BYTES>>>(P);
}